// round 1
// baseline (speedup 1.0000x reference)
#include <cuda_runtime.h>
#include <math.h>

// Problem dims (fixed)
#define BB   2
#define TT   2048
#define CC   1024
#define EE   1024
#define HH   16
#define HS   64
#define FF   4096
#define MM   (BB*TT)   // 4096 rows

// ---------------- scratch (static device globals; no allocation) ----------
__device__ float g_q   [MM*EE];
__device__ float g_k   [MM*EE];
__device__ float g_v   [MM*EE];
__device__ float g_attn[MM*EE];
__device__ float g_tmp [MM*CC];
__device__ float g_out1[MM*CC];
__device__ float g_ffh [MM*FF];
__device__ float g_out2[MM*CC];

// ---------------- SGEMM NN: C[M,N] = A[M,K] @ B[K,N] + bias (+opt GELU) ---
// 128x128 tile, BK=16, 256 threads, 8x8 per-thread register tile.
template<int EPI> // 0 = bias, 1 = bias + exact GELU
__global__ __launch_bounds__(256) void sgemm_nn(
    const float* __restrict__ A, const float* __restrict__ B,
    const float* __restrict__ bias, float* __restrict__ C,
    int M, int N, int K)
{
    __shared__ float As[16][132];  // transposed: As[k][m]
    __shared__ float Bs[16][132];  // Bs[k][n]

    const int tid = threadIdx.x;
    const int tx  = tid & 15;
    const int ty  = tid >> 4;
    const int m0  = blockIdx.y * 128;
    const int n0  = blockIdx.x * 128;

    float acc[8][8];
    #pragma unroll
    for (int i = 0; i < 8; i++)
        #pragma unroll
        for (int j = 0; j < 8; j++) acc[i][j] = 0.f;

    for (int k0 = 0; k0 < K; k0 += 16) {
        // A tile: 128 rows x 16 cols = 512 float4 loads, transposed store
        #pragma unroll
        for (int vv = 0; vv < 2; vv++) {
            int vec = tid + vv * 256;
            int row = vec >> 2;
            int cv  = vec & 3;
            float4 a4 = *(const float4*)(A + (size_t)(m0 + row) * K + k0 + cv * 4);
            As[cv*4+0][row] = a4.x;
            As[cv*4+1][row] = a4.y;
            As[cv*4+2][row] = a4.z;
            As[cv*4+3][row] = a4.w;
        }
        // B tile: 16 rows x 128 cols, direct vector store
        #pragma unroll
        for (int vv = 0; vv < 2; vv++) {
            int vec = tid + vv * 256;
            int row = vec >> 5;
            int cv  = vec & 31;
            *(float4*)(&Bs[row][cv*4]) =
                *(const float4*)(B + (size_t)(k0 + row) * N + n0 + cv * 4);
        }
        __syncthreads();

        #pragma unroll
        for (int kk = 0; kk < 16; kk++) {
            float a[8], b[8];
            *(float4*)(a)     = *(const float4*)(&As[kk][ty*8]);
            *(float4*)(a + 4) = *(const float4*)(&As[kk][ty*8 + 4]);
            *(float4*)(b)     = *(const float4*)(&Bs[kk][tx*8]);
            *(float4*)(b + 4) = *(const float4*)(&Bs[kk][tx*8 + 4]);
            #pragma unroll
            for (int i = 0; i < 8; i++)
                #pragma unroll
                for (int j = 0; j < 8; j++)
                    acc[i][j] = fmaf(a[i], b[j], acc[i][j]);
        }
        __syncthreads();
    }

    #pragma unroll
    for (int i = 0; i < 8; i++) {
        int m = m0 + ty*8 + i;
        #pragma unroll
        for (int j = 0; j < 8; j++) {
            int n = n0 + tx*8 + j;
            float val = acc[i][j] + bias[n];
            if (EPI == 1)
                val = 0.5f * val * (1.0f + erff(val * 0.70710678118654752f));
            C[(size_t)m * N + n] = val;
        }
    }
}

// ---------------- SGEMM NT: C[M,N] = A[M,K] @ Bt[N,K]^T + bias ------------
__global__ __launch_bounds__(256) void sgemm_nt(
    const float* __restrict__ A, const float* __restrict__ Bt,
    const float* __restrict__ bias, float* __restrict__ C,
    int M, int N, int K)
{
    __shared__ float As[16][132];
    __shared__ float Bs[16][132];

    const int tid = threadIdx.x;
    const int tx  = tid & 15;
    const int ty  = tid >> 4;
    const int m0  = blockIdx.y * 128;
    const int n0  = blockIdx.x * 128;

    float acc[8][8];
    #pragma unroll
    for (int i = 0; i < 8; i++)
        #pragma unroll
        for (int j = 0; j < 8; j++) acc[i][j] = 0.f;

    for (int k0 = 0; k0 < K; k0 += 16) {
        #pragma unroll
        for (int vv = 0; vv < 2; vv++) {
            int vec = tid + vv * 256;
            int row = vec >> 2;
            int cv  = vec & 3;
            float4 a4 = *(const float4*)(A + (size_t)(m0 + row) * K + k0 + cv * 4);
            As[cv*4+0][row] = a4.x;
            As[cv*4+1][row] = a4.y;
            As[cv*4+2][row] = a4.z;
            As[cv*4+3][row] = a4.w;
        }
        // Bt is [N,K] row-major; Bs[k][n] = Bt[n0+n][k0+k]
        #pragma unroll
        for (int vv = 0; vv < 2; vv++) {
            int vec = tid + vv * 256;
            int n   = vec >> 2;
            int cv  = vec & 3;
            float4 w4 = *(const float4*)(Bt + (size_t)(n0 + n) * K + k0 + cv * 4);
            Bs[cv*4+0][n] = w4.x;
            Bs[cv*4+1][n] = w4.y;
            Bs[cv*4+2][n] = w4.z;
            Bs[cv*4+3][n] = w4.w;
        }
        __syncthreads();

        #pragma unroll
        for (int kk = 0; kk < 16; kk++) {
            float a[8], b[8];
            *(float4*)(a)     = *(const float4*)(&As[kk][ty*8]);
            *(float4*)(a + 4) = *(const float4*)(&As[kk][ty*8 + 4]);
            *(float4*)(b)     = *(const float4*)(&Bs[kk][tx*8]);
            *(float4*)(b + 4) = *(const float4*)(&Bs[kk][tx*8 + 4]);
            #pragma unroll
            for (int i = 0; i < 8; i++)
                #pragma unroll
                for (int j = 0; j < 8; j++)
                    acc[i][j] = fmaf(a[i], b[j], acc[i][j]);
        }
        __syncthreads();
    }

    #pragma unroll
    for (int i = 0; i < 8; i++) {
        int m = m0 + ty*8 + i;
        #pragma unroll
        for (int j = 0; j < 8; j++) {
            int n = n0 + tx*8 + j;
            C[(size_t)m * N + n] = acc[i][j] + bias[n];
        }
    }
}

// ---------------- Fused flash attention (no mask), fp32 -------------------
// Block: 128 q-rows of one (b,h); streams 64-key K/V tiles with online softmax.
// Threads: 256 (16x16); per-thread tile 8 rows x 4 cols.
#define QS_STRIDE 132   // Qs[d][r], d in [0,64), r in [0,128)
#define KS_STRIDE 65    // Ks[key][d]
#define VS_STRIDE 68    // Vs[key][d]
#define PS_STRIDE 129   // Ps[key][r]
#define ATTN_SMEM ((64*QS_STRIDE + 64*KS_STRIDE + 64*VS_STRIDE + 64*PS_STRIDE) * 4)

__global__ __launch_bounds__(256) void attn_kernel(
    const float* __restrict__ Q, const float* __restrict__ K,
    const float* __restrict__ V, float* __restrict__ O)
{
    extern __shared__ float sm[];
    float* Qs = sm;                      // 64 x 132
    float* Ks = Qs + 64 * QS_STRIDE;     // 64 x 65
    float* Vs = Ks + 64 * KS_STRIDE;     // 64 x 68
    float* Ps = Vs + 64 * VS_STRIDE;     // 64 x 129

    const int tid = threadIdx.x;
    const int tx  = tid & 15;
    const int ty  = tid >> 4;
    const int q0  = blockIdx.x * 128;
    const int bh  = blockIdx.y;
    const int b   = bh / HH;
    const int h   = bh % HH;
    const size_t base = ((size_t)b * TT) * EE + (size_t)h * HS;

    // Load Q tile transposed: Qs[d][r]
    #pragma unroll
    for (int vv = 0; vv < 8; vv++) {
        int vec = tid + vv * 256;
        int row = vec >> 4;
        int dv  = vec & 15;
        float4 q4 = *(const float4*)(Q + base + (size_t)(q0 + row) * EE + dv * 4);
        Qs[(dv*4+0)*QS_STRIDE + row] = q4.x;
        Qs[(dv*4+1)*QS_STRIDE + row] = q4.y;
        Qs[(dv*4+2)*QS_STRIDE + row] = q4.z;
        Qs[(dv*4+3)*QS_STRIDE + row] = q4.w;
    }

    float m[8], l[8], o[8][4];
    #pragma unroll
    for (int i = 0; i < 8; i++) {
        m[i] = -1e30f; l[i] = 0.f;
        #pragma unroll
        for (int j = 0; j < 4; j++) o[i][j] = 0.f;
    }

    const int r0 = ty * 8;
    const int c0 = tx * 4;

    for (int s0 = 0; s0 < TT; s0 += 64) {
        __syncthreads();  // protect Qs(first iter)/Ks/Vs/Ps reuse
        // Load K/V tiles (64 x 64 each)
        #pragma unroll
        for (int vv = 0; vv < 4; vv++) {
            int vec = tid + vv * 256;
            int key = vec >> 4;
            int dv  = vec & 15;
            float4 k4 = *(const float4*)(K + base + (size_t)(s0 + key) * EE + dv * 4);
            Ks[key*KS_STRIDE + dv*4+0] = k4.x;
            Ks[key*KS_STRIDE + dv*4+1] = k4.y;
            Ks[key*KS_STRIDE + dv*4+2] = k4.z;
            Ks[key*KS_STRIDE + dv*4+3] = k4.w;
            float4 v4 = *(const float4*)(V + base + (size_t)(s0 + key) * EE + dv * 4);
            *(float4*)(&Vs[key*VS_STRIDE + dv*4]) = v4;
        }
        __syncthreads();

        // GEMM1: S = Q @ K^T (128 x 64, reduce over HS=64)
        float s[8][4];
        #pragma unroll
        for (int i = 0; i < 8; i++)
            #pragma unroll
            for (int j = 0; j < 4; j++) s[i][j] = 0.f;

        #pragma unroll 8
        for (int kk = 0; kk < 64; kk++) {
            float a[8];
            *(float4*)(a)     = *(const float4*)(&Qs[kk*QS_STRIDE + r0]);
            *(float4*)(a + 4) = *(const float4*)(&Qs[kk*QS_STRIDE + r0 + 4]);
            float bb[4];
            #pragma unroll
            for (int j = 0; j < 4; j++) bb[j] = Ks[(c0 + j)*KS_STRIDE + kk];
            #pragma unroll
            for (int i = 0; i < 8; i++)
                #pragma unroll
                for (int j = 0; j < 4; j++)
                    s[i][j] = fmaf(a[i], bb[j], s[i][j]);
        }

        // Online softmax (row state shared across the 16 tx lanes of a ty group)
        #pragma unroll
        for (int i = 0; i < 8; i++) {
            float tmax = -1e30f;
            #pragma unroll
            for (int j = 0; j < 4; j++) {
                s[i][j] *= 0.125f;  // 1/sqrt(64)
                tmax = fmaxf(tmax, s[i][j]);
            }
            #pragma unroll
            for (int msk = 1; msk < 16; msk <<= 1)
                tmax = fmaxf(tmax, __shfl_xor_sync(0xffffffffu, tmax, msk));
            float nm   = fmaxf(m[i], tmax);
            float corr = __expf(m[i] - nm);
            float p[4], tsum = 0.f;
            #pragma unroll
            for (int j = 0; j < 4; j++) {
                p[j] = __expf(s[i][j] - nm);
                tsum += p[j];
            }
            #pragma unroll
            for (int msk = 1; msk < 16; msk <<= 1)
                tsum += __shfl_xor_sync(0xffffffffu, tsum, msk);
            l[i] = l[i] * corr + tsum;
            m[i] = nm;
            #pragma unroll
            for (int j = 0; j < 4; j++) {
                o[i][j] *= corr;
                Ps[(c0 + j)*PS_STRIDE + (r0 + i)] = p[j];
            }
        }
        __syncthreads();

        // GEMM2: O += P @ V (reduce over 64 keys)
        #pragma unroll 4
        for (int k2 = 0; k2 < 64; k2++) {
            float pf[8];
            #pragma unroll
            for (int i = 0; i < 8; i++) pf[i] = Ps[k2*PS_STRIDE + r0 + i];
            float4 vv4 = *(const float4*)(&Vs[k2*VS_STRIDE + c0]);
            float vf[4] = {vv4.x, vv4.y, vv4.z, vv4.w};
            #pragma unroll
            for (int i = 0; i < 8; i++)
                #pragma unroll
                for (int j = 0; j < 4; j++)
                    o[i][j] = fmaf(pf[i], vf[j], o[i][j]);
        }
    }

    #pragma unroll
    for (int i = 0; i < 8; i++) {
        float inv = 1.0f / l[i];
        #pragma unroll
        for (int j = 0; j < 4; j++)
            O[base + (size_t)(q0 + r0 + i) * EE + c0 + j] = o[i][j] * inv;
    }
}

// ---------------- residual add + LayerNorm (one block per row, C=1024) ----
__global__ __launch_bounds__(256) void add_ln(
    const float* __restrict__ a, const float* __restrict__ bsrc,
    const float* __restrict__ g, const float* __restrict__ beta,
    float* __restrict__ out)
{
    const int row = blockIdx.x;
    const int tid = threadIdx.x;
    const float4 av = ((const float4*)(a    + (size_t)row * CC))[tid];
    const float4 bv = ((const float4*)(bsrc + (size_t)row * CC))[tid];
    float4 v = make_float4(av.x + bv.x, av.y + bv.y, av.z + bv.z, av.w + bv.w);

    float s  = v.x + v.y + v.z + v.w;
    float ss = v.x*v.x + v.y*v.y + v.z*v.z + v.w*v.w;
    #pragma unroll
    for (int msk = 16; msk; msk >>= 1) {
        s  += __shfl_xor_sync(0xffffffffu, s,  msk);
        ss += __shfl_xor_sync(0xffffffffu, ss, msk);
    }
    __shared__ float ws[8], wss[8];
    __shared__ float mu_s, rstd_s;
    const int w = tid >> 5, lane = tid & 31;
    if (lane == 0) { ws[w] = s; wss[w] = ss; }
    __syncthreads();
    if (tid == 0) {
        float S = 0.f, SS = 0.f;
        #pragma unroll
        for (int i = 0; i < 8; i++) { S += ws[i]; SS += wss[i]; }
        float mu  = S * (1.0f / CC);
        float var = SS * (1.0f / CC) - mu * mu;
        mu_s   = mu;
        rstd_s = rsqrtf(var + 1e-5f);
    }
    __syncthreads();
    const float mu = mu_s, rstd = rstd_s;
    const float4 gv = ((const float4*)g)[tid];
    const float4 bv2 = ((const float4*)beta)[tid];
    float4 ov;
    ov.x = (v.x - mu) * rstd * gv.x + bv2.x;
    ov.y = (v.y - mu) * rstd * gv.y + bv2.y;
    ov.z = (v.z - mu) * rstd * gv.z + bv2.z;
    ov.w = (v.w - mu) * rstd * gv.w + bv2.w;
    ((float4*)(out + (size_t)row * CC))[tid] = ov;
}

// ---------------- launch ---------------------------------------------------
extern "C" void kernel_launch(void* const* d_in, const int* in_sizes, int n_in,
                              void* d_out, int out_size)
{
    const float* x     = (const float*)d_in[0];
    const float* Wq    = (const float*)d_in[1];
    const float* bq    = (const float*)d_in[2];
    const float* Wk    = (const float*)d_in[3];
    const float* bk    = (const float*)d_in[4];
    const float* Wv    = (const float*)d_in[5];
    const float* bv    = (const float*)d_in[6];
    const float* Wo    = (const float*)d_in[7];
    const float* bo    = (const float*)d_in[8];
    const float* ln1_g = (const float*)d_in[9];
    const float* ln1_b = (const float*)d_in[10];
    const float* W1    = (const float*)d_in[11];
    const float* b1    = (const float*)d_in[12];
    const float* W2    = (const float*)d_in[13];
    const float* b2    = (const float*)d_in[14];
    const float* ln2_g = (const float*)d_in[15];
    const float* ln2_b = (const float*)d_in[16];
    const float* Wc    = (const float*)d_in[17];
    const float* bc    = (const float*)d_in[18];
    float* out = (float*)d_out;

    float *q, *k, *v, *attn, *tmp, *out1, *ffh, *out2;
    cudaGetSymbolAddress((void**)&q,    g_q);
    cudaGetSymbolAddress((void**)&k,    g_k);
    cudaGetSymbolAddress((void**)&v,    g_v);
    cudaGetSymbolAddress((void**)&attn, g_attn);
    cudaGetSymbolAddress((void**)&tmp,  g_tmp);
    cudaGetSymbolAddress((void**)&out1, g_out1);
    cudaGetSymbolAddress((void**)&ffh,  g_ffh);
    cudaGetSymbolAddress((void**)&out2, g_out2);

    const dim3 thr(256);
    const dim3 grid_c(CC / 128, MM / 128);   // N=1024
    const dim3 grid_ff(FF / 128, MM / 128);  // N=4096

    // QKV projections
    sgemm_nn<0><<<grid_c, thr>>>(x, Wq, bq, q, MM, EE, CC);
    sgemm_nn<0><<<grid_c, thr>>>(x, Wk, bk, k, MM, EE, CC);
    sgemm_nn<0><<<grid_c, thr>>>(x, Wv, bv, v, MM, EE, CC);

    // Fused attention
    cudaFuncSetAttribute(attn_kernel,
                         cudaFuncAttributeMaxDynamicSharedMemorySize, ATTN_SMEM);
    attn_kernel<<<dim3(TT / 128, BB * HH), thr, ATTN_SMEM>>>(q, k, v, attn);

    // Output projection + residual + LN1
    sgemm_nn<0><<<grid_c, thr>>>(attn, Wo, bo, tmp, MM, CC, EE);
    add_ln<<<MM, thr>>>(x, tmp, ln1_g, ln1_b, out1);

    // FFN
    sgemm_nn<1><<<grid_ff, thr>>>(out1, W1, b1, ffh, MM, FF, CC);
    sgemm_nn<0><<<grid_c, thr>>>(ffh, W2, b2, tmp, MM, CC, FF);
    add_ln<<<MM, thr>>>(out1, tmp, ln2_g, ln2_b, out2);

    // Final pointwise conv: out = out2 @ Wc^T + bc
    sgemm_nt<<<grid_c, thr>>>(out2, Wc, bc, out, MM, CC, CC);
}

// round 3
// speedup vs baseline: 1.7911x; 1.7911x over previous
#include <cuda_runtime.h>
#include <cuda_bf16.h>
#include <math.h>
#include <stdint.h>

// Problem dims (fixed)
#define BB   2
#define TT   2048
#define CC   1024
#define EE   1024
#define HH   16
#define HS   64
#define FF   4096
#define MM   (BB*TT)   // 4096 rows

// ======================= scratch (static device globals) ===================
__device__ float g_q   [MM*EE];
__device__ float g_k   [MM*EE];
__device__ float g_v   [MM*EE];
__device__ float g_tmp [MM*CC];
__device__ float g_out1[MM*CC];
__device__ float g_out2[MM*CC];

__device__ __nv_bfloat16 g_xh [MM*CC],  g_xl [MM*CC];
__device__ __nv_bfloat16 g_ah [MM*EE],  g_al [MM*EE];
__device__ __nv_bfloat16 g_o1h[MM*CC],  g_o1l[MM*CC];
__device__ __nv_bfloat16 g_fh [MM*FF],  g_fl [MM*FF];
__device__ __nv_bfloat16 g_o2h[MM*CC],  g_o2l[MM*CC];
// transposed+split weights: [N, K] bf16
__device__ __nv_bfloat16 g_wqh[EE*CC],  g_wql[EE*CC];
__device__ __nv_bfloat16 g_wkh[EE*CC],  g_wkl[EE*CC];
__device__ __nv_bfloat16 g_wvh[EE*CC],  g_wvl[EE*CC];
__device__ __nv_bfloat16 g_woh[CC*EE],  g_wol[CC*EE];
__device__ __nv_bfloat16 g_w1h[FF*CC],  g_w1l[FF*CC];
__device__ __nv_bfloat16 g_w2h[CC*FF],  g_w2l[CC*FF];
__device__ __nv_bfloat16 g_wch[CC*CC],  g_wcl[CC*CC];

// ======================= small PTX helpers =================================
__device__ __forceinline__ uint32_t smem_u32(const void* p) {
    uint32_t a;
    asm("{ .reg .u64 t; cvta.to.shared.u64 t, %1; cvt.u32.u64 %0, t; }"
        : "=r"(a) : "l"(p));
    return a;
}
__device__ __forceinline__ void cp16(uint32_t saddr, const void* gaddr) {
    asm volatile("cp.async.cg.shared.global [%0], [%1], 16;"
                 :: "r"(saddr), "l"(gaddr) : "memory");
}
#define CP_COMMIT() asm volatile("cp.async.commit_group;" ::: "memory")
#define CP_WAIT(n)  asm volatile("cp.async.wait_group %0;" :: "n"(n) : "memory")

__device__ __forceinline__ void ldsm_x4(uint32_t r[4], uint32_t addr) {
    asm volatile("ldmatrix.sync.aligned.m8n8.x4.shared.b16 {%0,%1,%2,%3}, [%4];"
                 : "=r"(r[0]), "=r"(r[1]), "=r"(r[2]), "=r"(r[3]) : "r"(addr));
}
__device__ __forceinline__ void mma16816(float c[4],
    uint32_t a0, uint32_t a1, uint32_t a2, uint32_t a3, uint32_t b0, uint32_t b1)
{
    asm volatile(
        "mma.sync.aligned.m16n8k16.row.col.f32.bf16.bf16.f32 "
        "{%0,%1,%2,%3}, {%4,%5,%6,%7}, {%8,%9}, {%0,%1,%2,%3};"
        : "+f"(c[0]), "+f"(c[1]), "+f"(c[2]), "+f"(c[3])
        : "r"(a0), "r"(a1), "r"(a2), "r"(a3), "r"(b0), "r"(b1));
}

__device__ __forceinline__ void split1(float x, __nv_bfloat16& h, __nv_bfloat16& l) {
    h = __float2bfloat16_rn(x);
    l = __float2bfloat16_rn(x - __bfloat162float(h));
}

// ======================= conversion kernels ================================
__global__ __launch_bounds__(256) void convert_split(
    const float* __restrict__ in, __nv_bfloat16* __restrict__ hi,
    __nv_bfloat16* __restrict__ lo, int n)
{
    int idx = (blockIdx.x * blockDim.x + threadIdx.x) * 4;
    int stride = gridDim.x * blockDim.x * 4;
    for (; idx < n; idx += stride) {
        float4 v = *(const float4*)(in + idx);
        __nv_bfloat16 h0,h1,h2,h3,l0,l1,l2,l3;
        split1(v.x,h0,l0); split1(v.y,h1,l1); split1(v.z,h2,l2); split1(v.w,h3,l3);
        *(__nv_bfloat162*)(hi + idx)     = __halves2bfloat162(h0,h1);
        *(__nv_bfloat162*)(hi + idx + 2) = __halves2bfloat162(h2,h3);
        *(__nv_bfloat162*)(lo + idx)     = __halves2bfloat162(l0,l1);
        *(__nv_bfloat162*)(lo + idx + 2) = __halves2bfloat162(l2,l3);
    }
}

// W[K,N] fp32 -> Wt[N,K] bf16 hi/lo
__global__ __launch_bounds__(256) void transpose_split(
    const float* __restrict__ W, __nv_bfloat16* __restrict__ Thi,
    __nv_bfloat16* __restrict__ Tlo, int K, int N)
{
    __shared__ float t[32][33];
    int n0 = blockIdx.x * 32, k0 = blockIdx.y * 32;
    int tx = threadIdx.x, ty = threadIdx.y;
    #pragma unroll
    for (int s = 0; s < 32; s += 8)
        t[ty + s][tx] = W[(size_t)(k0 + ty + s) * N + n0 + tx];
    __syncthreads();
    #pragma unroll
    for (int s = 0; s < 32; s += 8) {
        float v = t[tx][ty + s];  // = W[k0+tx][n0+ty+s]
        __nv_bfloat16 h, l; split1(v, h, l);
        size_t o = (size_t)(n0 + ty + s) * K + k0 + tx;
        Thi[o] = h; Tlo[o] = l;
    }
}

// ======================= HMMA split-bf16 GEMM ==============================
// C[M,N] = A[M,K] @ B[N,K]^T + bias, 3-pass bf16 split, fp32 accum.
// CTA tile 128x128, BK=32, 256 threads (8 warps, warp tile 64x32).
// Double-buffered smem: 2 stages x (4 arrays x 128 rows x 64B) = 64KB.
// Row layout: 64B per row, XOR swizzle chunk' = chunk ^ ((row>>1)&3).
#define STAGE_BYTES 32768
#define ARR_A_HI 0
#define ARR_A_LO 8192
#define ARR_B_HI 16384
#define ARR_B_LO 24576
#define GEMM_SMEM (2*STAGE_BYTES)

__device__ __forceinline__ uint32_t sw_off(int row, int chunk) {
    return (uint32_t)(row * 64 + ((chunk ^ ((row >> 1) & 3)) << 4));
}

template<int GELU, int WF32, int WHILO>
__global__ __launch_bounds__(256) void gemm_mma(
    const __nv_bfloat16* __restrict__ Ahi, const __nv_bfloat16* __restrict__ Alo,
    const __nv_bfloat16* __restrict__ Bhi, const __nv_bfloat16* __restrict__ Blo,
    const float* __restrict__ bias,
    float* __restrict__ Cf, __nv_bfloat16* __restrict__ Chi,
    __nv_bfloat16* __restrict__ Clo,
    int M, int N, int K)
{
    extern __shared__ char sm[];
    const uint32_t su = smem_u32(sm);

    const int tid  = threadIdx.x;
    const int wid  = tid >> 5;
    const int lane = tid & 31;
    const int m0 = blockIdx.y * 128;
    const int n0 = blockIdx.x * 128;
    const int wm0 = (wid & 1) * 64;   // warp M offset in tile
    const int wn0 = (wid >> 1) * 32;  // warp N offset in tile

    // ---- load indexing (per thread: 2 rows x 4 arrays = 8 cp.async/chunk)
    const int lr = tid >> 2;   // 0..63
    const int lq = tid & 3;    // 16B chunk within 64B row

    float acc[4][4][4];
    #pragma unroll
    for (int mt = 0; mt < 4; mt++)
        #pragma unroll
        for (int nt = 0; nt < 4; nt++)
            #pragma unroll
            for (int i = 0; i < 4; i++) acc[mt][nt][i] = 0.f;

    const int nCh = K >> 5;

    // issue loads for chunk c into stage stg
    auto issue = [&](int c, int stg) {
        const uint32_t sbase = su + stg * STAGE_BYTES;
        #pragma unroll
        for (int h = 0; h < 2; h++) {
            const int r = lr + h * 64;
            const size_t gA = ((size_t)(m0 + r) * K + c * 32 + lq * 8) * 2;
            const size_t gB = ((size_t)(n0 + r) * K + c * 32 + lq * 8) * 2;
            const uint32_t so = sw_off(r, lq);
            cp16(sbase + ARR_A_HI + so, (const char*)Ahi + gA);
            cp16(sbase + ARR_A_LO + so, (const char*)Alo + gA);
            cp16(sbase + ARR_B_HI + so, (const char*)Bhi + gB);
            cp16(sbase + ARR_B_LO + so, (const char*)Blo + gB);
        }
    };

    issue(0, 0);
    CP_COMMIT();

    for (int c = 0; c < nCh; c++) {
        const int stg = c & 1;
        if (c + 1 < nCh) {
            issue(c + 1, stg ^ 1);
            CP_COMMIT();
            CP_WAIT(1);
        } else {
            CP_WAIT(0);
        }
        __syncthreads();

        const uint32_t sbase = su + stg * STAGE_BYTES;

        #pragma unroll
        for (int ks = 0; ks < 2; ks++) {
            // ---- B fragments (hi & lo), warp covers n = wn0..wn0+31
            uint32_t bh[4][2], bl[4][2];
            const int grp = lane >> 3, wi = lane & 7;
            const int brow_base = wn0 + wi + ((grp >> 1) << 3);
            const int bchunk = ks * 2 + (grp & 1);
            #pragma unroll
            for (int bt = 0; bt < 2; bt++) {
                uint32_t r4[4];
                const int br = brow_base + bt * 16;
                ldsm_x4(r4, sbase + ARR_B_HI + sw_off(br, bchunk));
                bh[bt*2][0]   = r4[0]; bh[bt*2][1]   = r4[1];
                bh[bt*2+1][0] = r4[2]; bh[bt*2+1][1] = r4[3];
            }
            #pragma unroll
            for (int bt = 0; bt < 2; bt++) {
                uint32_t r4[4];
                const int br = brow_base + bt * 16;
                ldsm_x4(r4, sbase + ARR_B_LO + sw_off(br, bchunk));
                bl[bt*2][0]   = r4[0]; bl[bt*2][1]   = r4[1];
                bl[bt*2+1][0] = r4[2]; bl[bt*2+1][1] = r4[3];
            }

            // ---- A hi fragments
            const int arow = wm0 + (lane & 15);
            const int achunk = ks * 2 + (lane >> 4);
            uint32_t a[4][4];
            #pragma unroll
            for (int mt = 0; mt < 4; mt++)
                ldsm_x4(a[mt], sbase + ARR_A_HI + sw_off(arow + mt * 16, achunk));

            // hi*hi + hi*lo
            #pragma unroll
            for (int mt = 0; mt < 4; mt++)
                #pragma unroll
                for (int nt = 0; nt < 4; nt++) {
                    mma16816(acc[mt][nt], a[mt][0], a[mt][1], a[mt][2], a[mt][3],
                             bh[nt][0], bh[nt][1]);
                    mma16816(acc[mt][nt], a[mt][0], a[mt][1], a[mt][2], a[mt][3],
                             bl[nt][0], bl[nt][1]);
                }

            // ---- A lo fragments (reuse regs)
            #pragma unroll
            for (int mt = 0; mt < 4; mt++)
                ldsm_x4(a[mt], sbase + ARR_A_LO + sw_off(arow + mt * 16, achunk));

            // lo*hi
            #pragma unroll
            for (int mt = 0; mt < 4; mt++)
                #pragma unroll
                for (int nt = 0; nt < 4; nt++)
                    mma16816(acc[mt][nt], a[mt][0], a[mt][1], a[mt][2], a[mt][3],
                             bh[nt][0], bh[nt][1]);
        }
        __syncthreads();
    }

    // ---- epilogue
    const int er = lane >> 2;          // row within 8
    const int ec = (lane & 3) * 2;     // col pair within 8
    #pragma unroll
    for (int mt = 0; mt < 4; mt++) {
        #pragma unroll
        for (int nt = 0; nt < 4; nt++) {
            const int col = n0 + wn0 + nt * 8 + ec;
            const float b0 = bias[col], b1 = bias[col + 1];
            const int rA = m0 + wm0 + mt * 16 + er;
            const int rB = rA + 8;
            float v00 = acc[mt][nt][0] + b0;
            float v01 = acc[mt][nt][1] + b1;
            float v10 = acc[mt][nt][2] + b0;
            float v11 = acc[mt][nt][3] + b1;
            if (GELU) {
                v00 = 0.5f * v00 * (1.0f + erff(v00 * 0.70710678118654752f));
                v01 = 0.5f * v01 * (1.0f + erff(v01 * 0.70710678118654752f));
                v10 = 0.5f * v10 * (1.0f + erff(v10 * 0.70710678118654752f));
                v11 = 0.5f * v11 * (1.0f + erff(v11 * 0.70710678118654752f));
            }
            if (WF32) {
                *(float2*)(Cf + (size_t)rA * N + col) = make_float2(v00, v01);
                *(float2*)(Cf + (size_t)rB * N + col) = make_float2(v10, v11);
            }
            if (WHILO) {
                __nv_bfloat16 h0,l0,h1,l1;
                split1(v00,h0,l0); split1(v01,h1,l1);
                *(__nv_bfloat162*)(Chi + (size_t)rA * N + col) = __halves2bfloat162(h0,h1);
                *(__nv_bfloat162*)(Clo + (size_t)rA * N + col) = __halves2bfloat162(l0,l1);
                split1(v10,h0,l0); split1(v11,h1,l1);
                *(__nv_bfloat162*)(Chi + (size_t)rB * N + col) = __halves2bfloat162(h0,h1);
                *(__nv_bfloat162*)(Clo + (size_t)rB * N + col) = __halves2bfloat162(l0,l1);
            }
        }
    }
}

// ======================= fused flash attention (fp32) ======================
// Writes output directly as hi/lo bf16 (feeds the Wo GEMM).
#define QS_STRIDE 132
#define KS_STRIDE 65
#define VS_STRIDE 68
#define PS_STRIDE 129
#define ATTN_SMEM ((64*QS_STRIDE + 64*KS_STRIDE + 64*VS_STRIDE + 64*PS_STRIDE) * 4)

__global__ __launch_bounds__(256) void attn_kernel(
    const float* __restrict__ Q, const float* __restrict__ K,
    const float* __restrict__ V,
    __nv_bfloat16* __restrict__ Ohi, __nv_bfloat16* __restrict__ Olo)
{
    extern __shared__ float smf[];
    float* Qs = smf;
    float* Ks = Qs + 64 * QS_STRIDE;
    float* Vs = Ks + 64 * KS_STRIDE;
    float* Ps = Vs + 64 * VS_STRIDE;

    const int tid = threadIdx.x;
    const int tx  = tid & 15;
    const int ty  = tid >> 4;
    const int q0  = blockIdx.x * 128;
    const int bh  = blockIdx.y;
    const int b   = bh / HH;
    const int h   = bh % HH;
    const size_t base = ((size_t)b * TT) * EE + (size_t)h * HS;

    #pragma unroll
    for (int vv = 0; vv < 8; vv++) {
        int vec = tid + vv * 256;
        int row = vec >> 4;
        int dv  = vec & 15;
        float4 q4 = *(const float4*)(Q + base + (size_t)(q0 + row) * EE + dv * 4);
        Qs[(dv*4+0)*QS_STRIDE + row] = q4.x;
        Qs[(dv*4+1)*QS_STRIDE + row] = q4.y;
        Qs[(dv*4+2)*QS_STRIDE + row] = q4.z;
        Qs[(dv*4+3)*QS_STRIDE + row] = q4.w;
    }

    float m[8], l[8], o[8][4];
    #pragma unroll
    for (int i = 0; i < 8; i++) {
        m[i] = -1e30f; l[i] = 0.f;
        #pragma unroll
        for (int j = 0; j < 4; j++) o[i][j] = 0.f;
    }

    const int r0 = ty * 8;
    const int c0 = tx * 4;

    for (int s0 = 0; s0 < TT; s0 += 64) {
        __syncthreads();
        #pragma unroll
        for (int vv = 0; vv < 4; vv++) {
            int vec = tid + vv * 256;
            int key = vec >> 4;
            int dv  = vec & 15;
            float4 k4 = *(const float4*)(K + base + (size_t)(s0 + key) * EE + dv * 4);
            Ks[key*KS_STRIDE + dv*4+0] = k4.x;
            Ks[key*KS_STRIDE + dv*4+1] = k4.y;
            Ks[key*KS_STRIDE + dv*4+2] = k4.z;
            Ks[key*KS_STRIDE + dv*4+3] = k4.w;
            float4 v4 = *(const float4*)(V + base + (size_t)(s0 + key) * EE + dv * 4);
            *(float4*)(&Vs[key*VS_STRIDE + dv*4]) = v4;
        }
        __syncthreads();

        float s[8][4];
        #pragma unroll
        for (int i = 0; i < 8; i++)
            #pragma unroll
            for (int j = 0; j < 4; j++) s[i][j] = 0.f;

        #pragma unroll 8
        for (int kk = 0; kk < 64; kk++) {
            float a[8];
            *(float4*)(a)     = *(const float4*)(&Qs[kk*QS_STRIDE + r0]);
            *(float4*)(a + 4) = *(const float4*)(&Qs[kk*QS_STRIDE + r0 + 4]);
            float bb[4];
            #pragma unroll
            for (int j = 0; j < 4; j++) bb[j] = Ks[(c0 + j)*KS_STRIDE + kk];
            #pragma unroll
            for (int i = 0; i < 8; i++)
                #pragma unroll
                for (int j = 0; j < 4; j++)
                    s[i][j] = fmaf(a[i], bb[j], s[i][j]);
        }

        #pragma unroll
        for (int i = 0; i < 8; i++) {
            float tmax = -1e30f;
            #pragma unroll
            for (int j = 0; j < 4; j++) {
                s[i][j] *= 0.125f;
                tmax = fmaxf(tmax, s[i][j]);
            }
            #pragma unroll
            for (int msk = 1; msk < 16; msk <<= 1)
                tmax = fmaxf(tmax, __shfl_xor_sync(0xffffffffu, tmax, msk));
            float nm   = fmaxf(m[i], tmax);
            float corr = __expf(m[i] - nm);
            float p[4], tsum = 0.f;
            #pragma unroll
            for (int j = 0; j < 4; j++) {
                p[j] = __expf(s[i][j] - nm);
                tsum += p[j];
            }
            #pragma unroll
            for (int msk = 1; msk < 16; msk <<= 1)
                tsum += __shfl_xor_sync(0xffffffffu, tsum, msk);
            l[i] = l[i] * corr + tsum;
            m[i] = nm;
            #pragma unroll
            for (int j = 0; j < 4; j++) {
                o[i][j] *= corr;
                Ps[(c0 + j)*PS_STRIDE + (r0 + i)] = p[j];
            }
        }
        __syncthreads();

        #pragma unroll 4
        for (int k2 = 0; k2 < 64; k2++) {
            float pf[8];
            #pragma unroll
            for (int i = 0; i < 8; i++) pf[i] = Ps[k2*PS_STRIDE + r0 + i];
            float4 vv4 = *(const float4*)(&Vs[k2*VS_STRIDE + c0]);
            float vf[4] = {vv4.x, vv4.y, vv4.z, vv4.w};
            #pragma unroll
            for (int i = 0; i < 8; i++)
                #pragma unroll
                for (int j = 0; j < 4; j++)
                    o[i][j] = fmaf(pf[i], vf[j], o[i][j]);
        }
    }

    #pragma unroll
    for (int i = 0; i < 8; i++) {
        float inv = 1.0f / l[i];
        size_t off = base + (size_t)(q0 + r0 + i) * EE + c0;
        float v0 = o[i][0]*inv, v1 = o[i][1]*inv, v2 = o[i][2]*inv, v3 = o[i][3]*inv;
        __nv_bfloat16 h0,l0,h1,l1,h2,l2,h3,l3;
        split1(v0,h0,l0); split1(v1,h1,l1); split1(v2,h2,l2); split1(v3,h3,l3);
        *(__nv_bfloat162*)(Ohi + off)     = __halves2bfloat162(h0,h1);
        *(__nv_bfloat162*)(Ohi + off + 2) = __halves2bfloat162(h2,h3);
        *(__nv_bfloat162*)(Olo + off)     = __halves2bfloat162(l0,l1);
        *(__nv_bfloat162*)(Olo + off + 2) = __halves2bfloat162(l2,l3);
    }
}

// ======================= residual add + LayerNorm ==========================
__global__ __launch_bounds__(256) void add_ln(
    const float* __restrict__ a, const float* __restrict__ bsrc,
    const float* __restrict__ g, const float* __restrict__ beta,
    float* __restrict__ out,
    __nv_bfloat16* __restrict__ hi, __nv_bfloat16* __restrict__ lo)
{
    const int row = blockIdx.x;
    const int tid = threadIdx.x;
    const float4 av = ((const float4*)(a    + (size_t)row * CC))[tid];
    const float4 bv = ((const float4*)(bsrc + (size_t)row * CC))[tid];
    float4 v = make_float4(av.x + bv.x, av.y + bv.y, av.z + bv.z, av.w + bv.w);

    float s  = v.x + v.y + v.z + v.w;
    float ss = v.x*v.x + v.y*v.y + v.z*v.z + v.w*v.w;
    #pragma unroll
    for (int msk = 16; msk; msk >>= 1) {
        s  += __shfl_xor_sync(0xffffffffu, s,  msk);
        ss += __shfl_xor_sync(0xffffffffu, ss, msk);
    }
    __shared__ float ws[8], wss[8];
    __shared__ float mu_s, rstd_s;
    const int w = tid >> 5, lane = tid & 31;
    if (lane == 0) { ws[w] = s; wss[w] = ss; }
    __syncthreads();
    if (tid == 0) {
        float S = 0.f, SS = 0.f;
        #pragma unroll
        for (int i = 0; i < 8; i++) { S += ws[i]; SS += wss[i]; }
        float mu  = S * (1.0f / CC);
        float var = SS * (1.0f / CC) - mu * mu;
        mu_s   = mu;
        rstd_s = rsqrtf(var + 1e-5f);
    }
    __syncthreads();
    const float mu = mu_s, rstd = rstd_s;
    const float4 gv = ((const float4*)g)[tid];
    const float4 bv2 = ((const float4*)beta)[tid];
    float4 ov;
    ov.x = (v.x - mu) * rstd * gv.x + bv2.x;
    ov.y = (v.y - mu) * rstd * gv.y + bv2.y;
    ov.z = (v.z - mu) * rstd * gv.z + bv2.z;
    ov.w = (v.w - mu) * rstd * gv.w + bv2.w;
    ((float4*)(out + (size_t)row * CC))[tid] = ov;

    if (hi) {
        __nv_bfloat16 h0,h1,h2,h3,l0,l1,l2,l3;
        split1(ov.x,h0,l0); split1(ov.y,h1,l1); split1(ov.z,h2,l2); split1(ov.w,h3,l3);
        size_t o = (size_t)row * CC + tid * 4;
        *(__nv_bfloat162*)(hi + o)     = __halves2bfloat162(h0,h1);
        *(__nv_bfloat162*)(hi + o + 2) = __halves2bfloat162(h2,h3);
        *(__nv_bfloat162*)(lo + o)     = __halves2bfloat162(l0,l1);
        *(__nv_bfloat162*)(lo + o + 2) = __halves2bfloat162(l2,l3);
    }
}

// ======================= launch ============================================
extern "C" void kernel_launch(void* const* d_in, const int* in_sizes, int n_in,
                              void* d_out, int out_size)
{
    const float* x     = (const float*)d_in[0];
    const float* Wq    = (const float*)d_in[1];
    const float* bq    = (const float*)d_in[2];
    const float* Wk    = (const float*)d_in[3];
    const float* bk    = (const float*)d_in[4];
    const float* Wv    = (const float*)d_in[5];
    const float* bv    = (const float*)d_in[6];
    const float* Wo    = (const float*)d_in[7];
    const float* bo    = (const float*)d_in[8];
    const float* ln1_g = (const float*)d_in[9];
    const float* ln1_b = (const float*)d_in[10];
    const float* W1    = (const float*)d_in[11];
    const float* b1    = (const float*)d_in[12];
    const float* W2    = (const float*)d_in[13];
    const float* b2    = (const float*)d_in[14];
    const float* ln2_g = (const float*)d_in[15];
    const float* ln2_b = (const float*)d_in[16];
    const float* Wc    = (const float*)d_in[17];
    const float* bc    = (const float*)d_in[18];
    float* out = (float*)d_out;

    float *q, *k, *v, *tmp, *out1, *out2;
    cudaGetSymbolAddress((void**)&q,    g_q);
    cudaGetSymbolAddress((void**)&k,    g_k);
    cudaGetSymbolAddress((void**)&v,    g_v);
    cudaGetSymbolAddress((void**)&tmp,  g_tmp);
    cudaGetSymbolAddress((void**)&out1, g_out1);
    cudaGetSymbolAddress((void**)&out2, g_out2);

    __nv_bfloat16 *xh,*xl,*ah,*al,*o1h,*o1l,*fh,*fl,*o2h,*o2l;
    __nv_bfloat16 *wqh,*wql,*wkh,*wkl,*wvh,*wvl,*woh,*wol,*w1h,*w1l,*w2h,*w2l,*wch,*wcl;
    cudaGetSymbolAddress((void**)&xh,  g_xh);  cudaGetSymbolAddress((void**)&xl,  g_xl);
    cudaGetSymbolAddress((void**)&ah,  g_ah);  cudaGetSymbolAddress((void**)&al,  g_al);
    cudaGetSymbolAddress((void**)&o1h, g_o1h); cudaGetSymbolAddress((void**)&o1l, g_o1l);
    cudaGetSymbolAddress((void**)&fh,  g_fh);  cudaGetSymbolAddress((void**)&fl,  g_fl);
    cudaGetSymbolAddress((void**)&o2h, g_o2h); cudaGetSymbolAddress((void**)&o2l, g_o2l);
    cudaGetSymbolAddress((void**)&wqh, g_wqh); cudaGetSymbolAddress((void**)&wql, g_wql);
    cudaGetSymbolAddress((void**)&wkh, g_wkh); cudaGetSymbolAddress((void**)&wkl, g_wkl);
    cudaGetSymbolAddress((void**)&wvh, g_wvh); cudaGetSymbolAddress((void**)&wvl, g_wvl);
    cudaGetSymbolAddress((void**)&woh, g_woh); cudaGetSymbolAddress((void**)&wol, g_wol);
    cudaGetSymbolAddress((void**)&w1h, g_w1h); cudaGetSymbolAddress((void**)&w1l, g_w1l);
    cudaGetSymbolAddress((void**)&w2h, g_w2h); cudaGetSymbolAddress((void**)&w2l, g_w2l);
    cudaGetSymbolAddress((void**)&wch, g_wch); cudaGetSymbolAddress((void**)&wcl, g_wcl);

    cudaFuncSetAttribute(gemm_mma<0,1,0>,
                         cudaFuncAttributeMaxDynamicSharedMemorySize, GEMM_SMEM);
    cudaFuncSetAttribute(gemm_mma<1,0,1>,
                         cudaFuncAttributeMaxDynamicSharedMemorySize, GEMM_SMEM);
    cudaFuncSetAttribute(attn_kernel,
                         cudaFuncAttributeMaxDynamicSharedMemorySize, ATTN_SMEM);

    const dim3 tb(32, 8);

    // --- weight prep (transpose + split) ---
    transpose_split<<<dim3(EE/32, CC/32), tb>>>(Wq, wqh, wql, CC, EE);
    transpose_split<<<dim3(EE/32, CC/32), tb>>>(Wk, wkh, wkl, CC, EE);
    transpose_split<<<dim3(EE/32, CC/32), tb>>>(Wv, wvh, wvl, CC, EE);
    transpose_split<<<dim3(CC/32, EE/32), tb>>>(Wo, woh, wol, EE, CC);
    transpose_split<<<dim3(FF/32, CC/32), tb>>>(W1, w1h, w1l, CC, FF);
    transpose_split<<<dim3(CC/32, FF/32), tb>>>(W2, w2h, w2l, FF, CC);
    convert_split<<<1024, 256>>>(Wc, wch, wcl, CC*CC);   // Wc already [N,K]

    // --- x split ---
    convert_split<<<2048, 256>>>(x, xh, xl, MM*CC);

    // --- QKV projections ---
    const dim3 gC(CC/128, MM/128);   // (8, 32)
    const dim3 gF(FF/128, MM/128);   // (32, 32)
    gemm_mma<0,1,0><<<gC, 256, GEMM_SMEM>>>(xh, xl, wqh, wql, bq, q, nullptr, nullptr, MM, EE, CC);
    gemm_mma<0,1,0><<<gC, 256, GEMM_SMEM>>>(xh, xl, wkh, wkl, bk, k, nullptr, nullptr, MM, EE, CC);
    gemm_mma<0,1,0><<<gC, 256, GEMM_SMEM>>>(xh, xl, wvh, wvl, bv, v, nullptr, nullptr, MM, EE, CC);

    // --- attention (fp32 compute, hi/lo bf16 output) ---
    attn_kernel<<<dim3(TT/128, BB*HH), 256, ATTN_SMEM>>>(q, k, v, ah, al);

    // --- output projection + residual + LN1 ---
    gemm_mma<0,1,0><<<gC, 256, GEMM_SMEM>>>(ah, al, woh, wol, bo, tmp, nullptr, nullptr, MM, CC, EE);
    add_ln<<<MM, 256>>>(x, tmp, ln1_g, ln1_b, out1, o1h, o1l);

    // --- FFN ---
    gemm_mma<1,0,1><<<gF, 256, GEMM_SMEM>>>(o1h, o1l, w1h, w1l, b1, nullptr, fh, fl, MM, FF, CC);
    gemm_mma<0,1,0><<<gC, 256, GEMM_SMEM>>>(fh, fl, w2h, w2l, b2, tmp, nullptr, nullptr, MM, CC, FF);
    add_ln<<<MM, 256>>>(out1, tmp, ln2_g, ln2_b, out2, o2h, o2l);

    // --- final pointwise conv: out = out2 @ Wc^T + bc ---
    gemm_mma<0,1,0><<<gC, 256, GEMM_SMEM>>>(o2h, o2l, wch, wcl, bc, out, nullptr, nullptr, MM, CC, CC);
}

// round 4
// speedup vs baseline: 2.5230x; 1.4086x over previous
#include <cuda_runtime.h>
#include <cuda_bf16.h>
#include <math.h>
#include <stdint.h>

// Problem dims (fixed)
#define BB   2
#define TT   2048
#define CC   1024
#define EE   1024
#define HH   16
#define HS   64
#define FF   4096
#define MM   (BB*TT)   // 4096 rows

// ======================= scratch (static device globals) ===================
__device__ float g_tmp [MM*CC];
__device__ float g_out1[MM*CC];
__device__ float g_out2[MM*CC];

__device__ __nv_bfloat16 g_xh [MM*CC],  g_xl [MM*CC];
__device__ __nv_bfloat16 g_qbh[MM*EE],  g_qbl[MM*EE];
__device__ __nv_bfloat16 g_kbh[MM*EE],  g_kbl[MM*EE];
__device__ __nv_bfloat16 g_vbh[MM*EE],  g_vbl[MM*EE];
__device__ __nv_bfloat16 g_ah [MM*EE],  g_al [MM*EE];
__device__ __nv_bfloat16 g_o1h[MM*CC],  g_o1l[MM*CC];
__device__ __nv_bfloat16 g_fh [MM*FF],  g_fl [MM*FF];
__device__ __nv_bfloat16 g_o2h[MM*CC],  g_o2l[MM*CC];
// transposed+split weights: [N, K] bf16
__device__ __nv_bfloat16 g_wqh[EE*CC],  g_wql[EE*CC];
__device__ __nv_bfloat16 g_wkh[EE*CC],  g_wkl[EE*CC];
__device__ __nv_bfloat16 g_wvh[EE*CC],  g_wvl[EE*CC];
__device__ __nv_bfloat16 g_woh[CC*EE],  g_wol[CC*EE];
__device__ __nv_bfloat16 g_w1h[FF*CC],  g_w1l[FF*CC];
__device__ __nv_bfloat16 g_w2h[CC*FF],  g_w2l[CC*FF];
__device__ __nv_bfloat16 g_wch[CC*CC],  g_wcl[CC*CC];

// ======================= small PTX helpers =================================
__device__ __forceinline__ uint32_t smem_u32(const void* p) {
    uint32_t a;
    asm("{ .reg .u64 t; cvta.to.shared.u64 t, %1; cvt.u32.u64 %0, t; }"
        : "=r"(a) : "l"(p));
    return a;
}
__device__ __forceinline__ void cp16(uint32_t saddr, const void* gaddr) {
    asm volatile("cp.async.cg.shared.global [%0], [%1], 16;"
                 :: "r"(saddr), "l"(gaddr) : "memory");
}
#define CP_COMMIT() asm volatile("cp.async.commit_group;" ::: "memory")
#define CP_WAIT(n)  asm volatile("cp.async.wait_group %0;" :: "n"(n) : "memory")

__device__ __forceinline__ void ldsm_x4(uint32_t r[4], uint32_t addr) {
    asm volatile("ldmatrix.sync.aligned.m8n8.x4.shared.b16 {%0,%1,%2,%3}, [%4];"
                 : "=r"(r[0]), "=r"(r[1]), "=r"(r[2]), "=r"(r[3]) : "r"(addr));
}
__device__ __forceinline__ void mma16816(float c[4],
    uint32_t a0, uint32_t a1, uint32_t a2, uint32_t a3, uint32_t b0, uint32_t b1)
{
    asm volatile(
        "mma.sync.aligned.m16n8k16.row.col.f32.bf16.bf16.f32 "
        "{%0,%1,%2,%3}, {%4,%5,%6,%7}, {%8,%9}, {%0,%1,%2,%3};"
        : "+f"(c[0]), "+f"(c[1]), "+f"(c[2]), "+f"(c[3])
        : "r"(a0), "r"(a1), "r"(a2), "r"(a3), "r"(b0), "r"(b1));
}

__device__ __forceinline__ void split1(float x, __nv_bfloat16& h, __nv_bfloat16& l) {
    h = __float2bfloat16_rn(x);
    l = __float2bfloat16_rn(x - __bfloat162float(h));
}
__device__ __forceinline__ uint32_t packbf(__nv_bfloat16 a, __nv_bfloat16 b) {
    __nv_bfloat162 t = __halves2bfloat162(a, b);
    return *(uint32_t*)&t;
}

// ======================= conversion kernels ================================
__global__ __launch_bounds__(256) void convert_split(
    const float* __restrict__ in, __nv_bfloat16* __restrict__ hi,
    __nv_bfloat16* __restrict__ lo, int n)
{
    int idx = (blockIdx.x * blockDim.x + threadIdx.x) * 4;
    int stride = gridDim.x * blockDim.x * 4;
    for (; idx < n; idx += stride) {
        float4 v = *(const float4*)(in + idx);
        __nv_bfloat16 h0,h1,h2,h3,l0,l1,l2,l3;
        split1(v.x,h0,l0); split1(v.y,h1,l1); split1(v.z,h2,l2); split1(v.w,h3,l3);
        *(__nv_bfloat162*)(hi + idx)     = __halves2bfloat162(h0,h1);
        *(__nv_bfloat162*)(hi + idx + 2) = __halves2bfloat162(h2,h3);
        *(__nv_bfloat162*)(lo + idx)     = __halves2bfloat162(l0,l1);
        *(__nv_bfloat162*)(lo + idx + 2) = __halves2bfloat162(l2,l3);
    }
}

// W[K,N] fp32 -> Wt[N,K] bf16 hi/lo
__global__ __launch_bounds__(256) void transpose_split(
    const float* __restrict__ W, __nv_bfloat16* __restrict__ Thi,
    __nv_bfloat16* __restrict__ Tlo, int K, int N)
{
    __shared__ float t[32][33];
    int n0 = blockIdx.x * 32, k0 = blockIdx.y * 32;
    int tx = threadIdx.x, ty = threadIdx.y;
    #pragma unroll
    for (int s = 0; s < 32; s += 8)
        t[ty + s][tx] = W[(size_t)(k0 + ty + s) * N + n0 + tx];
    __syncthreads();
    #pragma unroll
    for (int s = 0; s < 32; s += 8) {
        float v = t[tx][ty + s];  // = W[k0+tx][n0+ty+s]
        __nv_bfloat16 h, l; split1(v, h, l);
        size_t o = (size_t)(n0 + ty + s) * K + k0 + tx;
        Thi[o] = h; Tlo[o] = l;
    }
}

// ======================= HMMA split-bf16 GEMM ==============================
// C[M,N] = A[M,K] @ B[N,K]^T + bias, 3-pass bf16 split, fp32 accum.
#define STAGE_BYTES 32768
#define ARR_A_HI 0
#define ARR_A_LO 8192
#define ARR_B_HI 16384
#define ARR_B_LO 24576
#define GEMM_SMEM (2*STAGE_BYTES)

__device__ __forceinline__ uint32_t sw_off(int row, int chunk) {
    return (uint32_t)(row * 64 + ((chunk ^ ((row >> 1) & 3)) << 4));
}

template<int GELU, int WF32, int WHILO>
__global__ __launch_bounds__(256) void gemm_mma(
    const __nv_bfloat16* __restrict__ Ahi, const __nv_bfloat16* __restrict__ Alo,
    const __nv_bfloat16* __restrict__ Bhi, const __nv_bfloat16* __restrict__ Blo,
    const float* __restrict__ bias,
    float* __restrict__ Cf, __nv_bfloat16* __restrict__ Chi,
    __nv_bfloat16* __restrict__ Clo,
    int M, int N, int K)
{
    extern __shared__ char sm[];
    const uint32_t su = smem_u32(sm);

    const int tid  = threadIdx.x;
    const int wid  = tid >> 5;
    const int lane = tid & 31;
    const int m0 = blockIdx.y * 128;
    const int n0 = blockIdx.x * 128;
    const int wm0 = (wid & 1) * 64;
    const int wn0 = (wid >> 1) * 32;

    const int lr = tid >> 2;
    const int lq = tid & 3;

    float acc[4][4][4];
    #pragma unroll
    for (int mt = 0; mt < 4; mt++)
        #pragma unroll
        for (int nt = 0; nt < 4; nt++)
            #pragma unroll
            for (int i = 0; i < 4; i++) acc[mt][nt][i] = 0.f;

    const int nCh = K >> 5;

    auto issue = [&](int c, int stg) {
        const uint32_t sbase = su + stg * STAGE_BYTES;
        #pragma unroll
        for (int h = 0; h < 2; h++) {
            const int r = lr + h * 64;
            const size_t gA = ((size_t)(m0 + r) * K + c * 32 + lq * 8) * 2;
            const size_t gB = ((size_t)(n0 + r) * K + c * 32 + lq * 8) * 2;
            const uint32_t so = sw_off(r, lq);
            cp16(sbase + ARR_A_HI + so, (const char*)Ahi + gA);
            cp16(sbase + ARR_A_LO + so, (const char*)Alo + gA);
            cp16(sbase + ARR_B_HI + so, (const char*)Bhi + gB);
            cp16(sbase + ARR_B_LO + so, (const char*)Blo + gB);
        }
    };

    issue(0, 0);
    CP_COMMIT();

    for (int c = 0; c < nCh; c++) {
        const int stg = c & 1;
        if (c + 1 < nCh) {
            issue(c + 1, stg ^ 1);
            CP_COMMIT();
            CP_WAIT(1);
        } else {
            CP_WAIT(0);
        }
        __syncthreads();

        const uint32_t sbase = su + stg * STAGE_BYTES;

        #pragma unroll
        for (int ks = 0; ks < 2; ks++) {
            uint32_t bh[4][2], bl[4][2];
            const int grp = lane >> 3, wi = lane & 7;
            const int brow_base = wn0 + wi + ((grp >> 1) << 3);
            const int bchunk = ks * 2 + (grp & 1);
            #pragma unroll
            for (int bt = 0; bt < 2; bt++) {
                uint32_t r4[4];
                const int br = brow_base + bt * 16;
                ldsm_x4(r4, sbase + ARR_B_HI + sw_off(br, bchunk));
                bh[bt*2][0]   = r4[0]; bh[bt*2][1]   = r4[1];
                bh[bt*2+1][0] = r4[2]; bh[bt*2+1][1] = r4[3];
            }
            #pragma unroll
            for (int bt = 0; bt < 2; bt++) {
                uint32_t r4[4];
                const int br = brow_base + bt * 16;
                ldsm_x4(r4, sbase + ARR_B_LO + sw_off(br, bchunk));
                bl[bt*2][0]   = r4[0]; bl[bt*2][1]   = r4[1];
                bl[bt*2+1][0] = r4[2]; bl[bt*2+1][1] = r4[3];
            }

            const int arow = wm0 + (lane & 15);
            const int achunk = ks * 2 + (lane >> 4);
            uint32_t a[4][4];
            #pragma unroll
            for (int mt = 0; mt < 4; mt++)
                ldsm_x4(a[mt], sbase + ARR_A_HI + sw_off(arow + mt * 16, achunk));

            #pragma unroll
            for (int mt = 0; mt < 4; mt++)
                #pragma unroll
                for (int nt = 0; nt < 4; nt++) {
                    mma16816(acc[mt][nt], a[mt][0], a[mt][1], a[mt][2], a[mt][3],
                             bh[nt][0], bh[nt][1]);
                    mma16816(acc[mt][nt], a[mt][0], a[mt][1], a[mt][2], a[mt][3],
                             bl[nt][0], bl[nt][1]);
                }

            #pragma unroll
            for (int mt = 0; mt < 4; mt++)
                ldsm_x4(a[mt], sbase + ARR_A_LO + sw_off(arow + mt * 16, achunk));

            #pragma unroll
            for (int mt = 0; mt < 4; mt++)
                #pragma unroll
                for (int nt = 0; nt < 4; nt++)
                    mma16816(acc[mt][nt], a[mt][0], a[mt][1], a[mt][2], a[mt][3],
                             bh[nt][0], bh[nt][1]);
        }
        __syncthreads();
    }

    const int er = lane >> 2;
    const int ec = (lane & 3) * 2;
    #pragma unroll
    for (int mt = 0; mt < 4; mt++) {
        #pragma unroll
        for (int nt = 0; nt < 4; nt++) {
            const int col = n0 + wn0 + nt * 8 + ec;
            const float b0 = bias[col], b1 = bias[col + 1];
            const int rA = m0 + wm0 + mt * 16 + er;
            const int rB = rA + 8;
            float v00 = acc[mt][nt][0] + b0;
            float v01 = acc[mt][nt][1] + b1;
            float v10 = acc[mt][nt][2] + b0;
            float v11 = acc[mt][nt][3] + b1;
            if (GELU) {
                v00 = 0.5f * v00 * (1.0f + erff(v00 * 0.70710678118654752f));
                v01 = 0.5f * v01 * (1.0f + erff(v01 * 0.70710678118654752f));
                v10 = 0.5f * v10 * (1.0f + erff(v10 * 0.70710678118654752f));
                v11 = 0.5f * v11 * (1.0f + erff(v11 * 0.70710678118654752f));
            }
            if (WF32) {
                *(float2*)(Cf + (size_t)rA * N + col) = make_float2(v00, v01);
                *(float2*)(Cf + (size_t)rB * N + col) = make_float2(v10, v11);
            }
            if (WHILO) {
                __nv_bfloat16 h0,l0,h1,l1;
                split1(v00,h0,l0); split1(v01,h1,l1);
                *(__nv_bfloat162*)(Chi + (size_t)rA * N + col) = __halves2bfloat162(h0,h1);
                *(__nv_bfloat162*)(Clo + (size_t)rA * N + col) = __halves2bfloat162(l0,l1);
                split1(v10,h0,l0); split1(v11,h1,l1);
                *(__nv_bfloat162*)(Chi + (size_t)rB * N + col) = __halves2bfloat162(h0,h1);
                *(__nv_bfloat162*)(Clo + (size_t)rB * N + col) = __halves2bfloat162(l0,l1);
            }
        }
    }
}

// ======================= tensor-core flash attention =======================
// 128 q-rows/CTA, one (b,h). 64-key chunks. 8 warps, warp = 16 q-rows.
// S = Q K^T (3-pass split), online softmax in fragments, O += P V (3-pass).
// Smem: Qh/Ql [128][64], Kh/Kl [64][64], Vth/Vtl [64 dims][64 keys]; 128B rows.
#define ASM_QH 0
#define ASM_QL 16384
#define ASM_KH 32768
#define ASM_KL 40960
#define ASM_VH 49152
#define ASM_VL 57344
#define ATTN_SMEM 65536

__device__ __forceinline__ uint32_t sw8(int row, int ch) {
    return (uint32_t)(row * 128 + ((ch ^ (row & 7)) << 4));
}

__global__ void __launch_bounds__(256, 2) attn_mma(
    const __nv_bfloat16* __restrict__ Qh, const __nv_bfloat16* __restrict__ Ql,
    const __nv_bfloat16* __restrict__ Kh, const __nv_bfloat16* __restrict__ Kl,
    const __nv_bfloat16* __restrict__ Vh, const __nv_bfloat16* __restrict__ Vl,
    __nv_bfloat16* __restrict__ Ohi, __nv_bfloat16* __restrict__ Olo)
{
    extern __shared__ char sm[];
    const uint32_t su = smem_u32(sm);

    const int tid  = threadIdx.x;
    const int wid  = tid >> 5;
    const int lane = tid & 31;
    const int q0 = blockIdx.x * 128;
    const int bh = blockIdx.y;
    const int b  = bh >> 4;
    const int h  = bh & 15;
    const size_t base = ((size_t)b * TT) * EE + (size_t)h * HS;

    const int wm  = wid * 16;
    const int grp = lane >> 3, wi = lane & 7;

    // ---- Q tile load (once): 128 rows x 8 chunks per array
    #pragma unroll
    for (int i = 0; i < 4; i++) {
        int vec = tid + i * 256;
        int row = vec >> 3, ch = vec & 7;
        const size_t g = (base + (size_t)(q0 + row) * EE + ch * 8) * 2;
        cp16(su + ASM_QH + sw8(row, ch), (const char*)Qh + g);
        cp16(su + ASM_QL + sw8(row, ch), (const char*)Ql + g);
    }
    CP_COMMIT();

    float m0 = -1e30f, m1 = -1e30f, l0 = 0.f, l1 = 0.f;
    float oacc[8][4];
    #pragma unroll
    for (int nt = 0; nt < 8; nt++)
        #pragma unroll
        for (int i = 0; i < 4; i++) oacc[nt][i] = 0.f;

    for (int s0 = 0; s0 < TT; s0 += 64) {
        __syncthreads();   // all warps done reading K/V smem of prev chunk

        // K chunk via cp.async: 64 rows x 8 chunks per array
        #pragma unroll
        for (int i = 0; i < 2; i++) {
            int vec = tid + i * 256;
            int row = vec >> 3, ch = vec & 7;
            const size_t g = (base + (size_t)(s0 + row) * EE + ch * 8) * 2;
            cp16(su + ASM_KH + sw8(row, ch), (const char*)Kh + g);
            cp16(su + ASM_KL + sw8(row, ch), (const char*)Kl + g);
        }
        CP_COMMIT();

        // V chunk: load + transpose to Vt[dim][key]
        {
            const int key = tid >> 2, dg = tid & 3;
            const size_t gbase = base + (size_t)(s0 + key) * EE + dg * 16;
            uint4 vhr0 = *(const uint4*)(Vh + gbase);
            uint4 vhr1 = *(const uint4*)(Vh + gbase + 8);
            uint4 vlr0 = *(const uint4*)(Vl + gbase);
            uint4 vlr1 = *(const uint4*)(Vl + gbase + 8);
            const int kc = key >> 3;
            const uint32_t kb = (key & 7) * 2;
            const __nv_bfloat16* eh0 = (const __nv_bfloat16*)&vhr0;
            const __nv_bfloat16* eh1 = (const __nv_bfloat16*)&vhr1;
            const __nv_bfloat16* el0 = (const __nv_bfloat16*)&vlr0;
            const __nv_bfloat16* el1 = (const __nv_bfloat16*)&vlr1;
            #pragma unroll
            for (int j = 0; j < 8; j++) {
                int d0 = dg * 16 + j;
                int d1 = dg * 16 + 8 + j;
                *(__nv_bfloat16*)(sm + ASM_VH + sw8(d0, kc) + kb) = eh0[j];
                *(__nv_bfloat16*)(sm + ASM_VH + sw8(d1, kc) + kb) = eh1[j];
                *(__nv_bfloat16*)(sm + ASM_VL + sw8(d0, kc) + kb) = el0[j];
                *(__nv_bfloat16*)(sm + ASM_VL + sw8(d1, kc) + kb) = el1[j];
            }
        }
        CP_WAIT(0);
        __syncthreads();

        // ---- S = Q K^T, 3 passes ----
        float sacc[8][4];
        #pragma unroll
        for (int nt = 0; nt < 8; nt++)
            #pragma unroll
            for (int i = 0; i < 4; i++) sacc[nt][i] = 0.f;

        #pragma unroll
        for (int ks = 0; ks < 4; ks++) {
            const int arow = wm + (lane & 15);
            const int achunk = ks * 2 + (lane >> 4);
            uint32_t qa[4], qb[4];
            ldsm_x4(qa, su + ASM_QH + sw8(arow, achunk));
            ldsm_x4(qb, su + ASM_QL + sw8(arow, achunk));

            uint32_t kfh[8][2], kfl[8][2];
            #pragma unroll
            for (int bt = 0; bt < 4; bt++) {
                const int br = wi + ((grp >> 1) << 3) + bt * 16;
                const int bch = ks * 2 + (grp & 1);
                uint32_t r4[4];
                ldsm_x4(r4, su + ASM_KH + sw8(br, bch));
                kfh[bt*2][0] = r4[0]; kfh[bt*2][1] = r4[1];
                kfh[bt*2+1][0] = r4[2]; kfh[bt*2+1][1] = r4[3];
                ldsm_x4(r4, su + ASM_KL + sw8(br, bch));
                kfl[bt*2][0] = r4[0]; kfl[bt*2][1] = r4[1];
                kfl[bt*2+1][0] = r4[2]; kfl[bt*2+1][1] = r4[3];
            }
            #pragma unroll
            for (int nt = 0; nt < 8; nt++) {
                mma16816(sacc[nt], qa[0], qa[1], qa[2], qa[3], kfh[nt][0], kfh[nt][1]);
                mma16816(sacc[nt], qa[0], qa[1], qa[2], qa[3], kfl[nt][0], kfl[nt][1]);
                mma16816(sacc[nt], qb[0], qb[1], qb[2], qb[3], kfh[nt][0], kfh[nt][1]);
            }
        }

        // ---- online softmax ----
        float rmax0 = -1e30f, rmax1 = -1e30f;
        #pragma unroll
        for (int nt = 0; nt < 8; nt++) {
            #pragma unroll
            for (int i = 0; i < 4; i++) sacc[nt][i] *= 0.125f;
            rmax0 = fmaxf(rmax0, fmaxf(sacc[nt][0], sacc[nt][1]));
            rmax1 = fmaxf(rmax1, fmaxf(sacc[nt][2], sacc[nt][3]));
        }
        #pragma unroll
        for (int msk = 1; msk < 4; msk <<= 1) {
            rmax0 = fmaxf(rmax0, __shfl_xor_sync(0xffffffffu, rmax0, msk));
            rmax1 = fmaxf(rmax1, __shfl_xor_sync(0xffffffffu, rmax1, msk));
        }
        const float nm0 = fmaxf(m0, rmax0);
        const float nm1 = fmaxf(m1, rmax1);
        const float corr0 = __expf(m0 - nm0);
        const float corr1 = __expf(m1 - nm1);

        uint32_t pah[4][4], pal[4][4];
        float sum0 = 0.f, sum1 = 0.f;
        #pragma unroll
        for (int nt = 0; nt < 8; nt++) {
            float p0 = __expf(sacc[nt][0] - nm0);
            float p1 = __expf(sacc[nt][1] - nm0);
            float p2 = __expf(sacc[nt][2] - nm1);
            float p3 = __expf(sacc[nt][3] - nm1);
            sum0 += p0 + p1;
            sum1 += p2 + p3;
            __nv_bfloat16 h0,lo0,h1,lo1,h2,lo2,h3,lo3;
            split1(p0,h0,lo0); split1(p1,h1,lo1);
            split1(p2,h2,lo2); split1(p3,h3,lo3);
            const int kt = nt >> 1, hf = nt & 1;
            pah[kt][hf*2]   = packbf(h0, h1);
            pah[kt][hf*2+1] = packbf(h2, h3);
            pal[kt][hf*2]   = packbf(lo0, lo1);
            pal[kt][hf*2+1] = packbf(lo2, lo3);
        }
        #pragma unroll
        for (int msk = 1; msk < 4; msk <<= 1) {
            sum0 += __shfl_xor_sync(0xffffffffu, sum0, msk);
            sum1 += __shfl_xor_sync(0xffffffffu, sum1, msk);
        }
        l0 = l0 * corr0 + sum0;
        l1 = l1 * corr1 + sum1;
        m0 = nm0; m1 = nm1;
        #pragma unroll
        for (int nt = 0; nt < 8; nt++) {
            oacc[nt][0] *= corr0; oacc[nt][1] *= corr0;
            oacc[nt][2] *= corr1; oacc[nt][3] *= corr1;
        }

        // ---- O += P V, 3 passes ----
        #pragma unroll
        for (int ks = 0; ks < 4; ks++) {
            uint32_t vfh[8][2], vfl[8][2];
            #pragma unroll
            for (int bt = 0; bt < 4; bt++) {
                const int br = wi + ((grp >> 1) << 3) + bt * 16;
                const int bch = ks * 2 + (grp & 1);
                uint32_t r4[4];
                ldsm_x4(r4, su + ASM_VH + sw8(br, bch));
                vfh[bt*2][0] = r4[0]; vfh[bt*2][1] = r4[1];
                vfh[bt*2+1][0] = r4[2]; vfh[bt*2+1][1] = r4[3];
                ldsm_x4(r4, su + ASM_VL + sw8(br, bch));
                vfl[bt*2][0] = r4[0]; vfl[bt*2][1] = r4[1];
                vfl[bt*2+1][0] = r4[2]; vfl[bt*2+1][1] = r4[3];
            }
            #pragma unroll
            for (int nt = 0; nt < 8; nt++) {
                mma16816(oacc[nt], pah[ks][0], pah[ks][1], pah[ks][2], pah[ks][3],
                         vfh[nt][0], vfh[nt][1]);
                mma16816(oacc[nt], pal[ks][0], pal[ks][1], pal[ks][2], pal[ks][3],
                         vfh[nt][0], vfh[nt][1]);
                mma16816(oacc[nt], pah[ks][0], pah[ks][1], pah[ks][2], pah[ks][3],
                         vfl[nt][0], vfl[nt][1]);
            }
        }
    }

    // ---- epilogue ----
    const float inv0 = 1.0f / l0;
    const float inv1 = 1.0f / l1;
    const int r = lane >> 2;
    const int qcol = 2 * (lane & 3);
    const size_t row0 = base + (size_t)(q0 + wm + r) * EE;
    const size_t row1 = row0 + 8 * EE;
    #pragma unroll
    for (int nt = 0; nt < 8; nt++) {
        const int col = nt * 8 + qcol;
        float v0 = oacc[nt][0] * inv0, v1 = oacc[nt][1] * inv0;
        float v2 = oacc[nt][2] * inv1, v3 = oacc[nt][3] * inv1;
        __nv_bfloat16 h0,lo0,h1,lo1;
        split1(v0,h0,lo0); split1(v1,h1,lo1);
        *(__nv_bfloat162*)(Ohi + row0 + col) = __halves2bfloat162(h0,h1);
        *(__nv_bfloat162*)(Olo + row0 + col) = __halves2bfloat162(lo0,lo1);
        split1(v2,h0,lo0); split1(v3,h1,lo1);
        *(__nv_bfloat162*)(Ohi + row1 + col) = __halves2bfloat162(h0,h1);
        *(__nv_bfloat162*)(Olo + row1 + col) = __halves2bfloat162(lo0,lo1);
    }
}

// ======================= residual add + LayerNorm ==========================
__global__ __launch_bounds__(256) void add_ln(
    const float* __restrict__ a, const float* __restrict__ bsrc,
    const float* __restrict__ g, const float* __restrict__ beta,
    float* __restrict__ out,
    __nv_bfloat16* __restrict__ hi, __nv_bfloat16* __restrict__ lo)
{
    const int row = blockIdx.x;
    const int tid = threadIdx.x;
    const float4 av = ((const float4*)(a    + (size_t)row * CC))[tid];
    const float4 bv = ((const float4*)(bsrc + (size_t)row * CC))[tid];
    float4 v = make_float4(av.x + bv.x, av.y + bv.y, av.z + bv.z, av.w + bv.w);

    float s  = v.x + v.y + v.z + v.w;
    float ss = v.x*v.x + v.y*v.y + v.z*v.z + v.w*v.w;
    #pragma unroll
    for (int msk = 16; msk; msk >>= 1) {
        s  += __shfl_xor_sync(0xffffffffu, s,  msk);
        ss += __shfl_xor_sync(0xffffffffu, ss, msk);
    }
    __shared__ float ws[8], wss[8];
    __shared__ float mu_s, rstd_s;
    const int w = tid >> 5, lane = tid & 31;
    if (lane == 0) { ws[w] = s; wss[w] = ss; }
    __syncthreads();
    if (tid == 0) {
        float S = 0.f, SS = 0.f;
        #pragma unroll
        for (int i = 0; i < 8; i++) { S += ws[i]; SS += wss[i]; }
        float mu  = S * (1.0f / CC);
        float var = SS * (1.0f / CC) - mu * mu;
        mu_s   = mu;
        rstd_s = rsqrtf(var + 1e-5f);
    }
    __syncthreads();
    const float mu = mu_s, rstd = rstd_s;
    const float4 gv = ((const float4*)g)[tid];
    const float4 bv2 = ((const float4*)beta)[tid];
    float4 ov;
    ov.x = (v.x - mu) * rstd * gv.x + bv2.x;
    ov.y = (v.y - mu) * rstd * gv.y + bv2.y;
    ov.z = (v.z - mu) * rstd * gv.z + bv2.z;
    ov.w = (v.w - mu) * rstd * gv.w + bv2.w;
    ((float4*)(out + (size_t)row * CC))[tid] = ov;

    if (hi) {
        __nv_bfloat16 h0,h1,h2,h3,l0,l1,l2,l3;
        split1(ov.x,h0,l0); split1(ov.y,h1,l1); split1(ov.z,h2,l2); split1(ov.w,h3,l3);
        size_t o = (size_t)row * CC + tid * 4;
        *(__nv_bfloat162*)(hi + o)     = __halves2bfloat162(h0,h1);
        *(__nv_bfloat162*)(hi + o + 2) = __halves2bfloat162(h2,h3);
        *(__nv_bfloat162*)(lo + o)     = __halves2bfloat162(l0,l1);
        *(__nv_bfloat162*)(lo + o + 2) = __halves2bfloat162(l2,l3);
    }
}

// ======================= launch ============================================
extern "C" void kernel_launch(void* const* d_in, const int* in_sizes, int n_in,
                              void* d_out, int out_size)
{
    const float* x     = (const float*)d_in[0];
    const float* Wq    = (const float*)d_in[1];
    const float* bq    = (const float*)d_in[2];
    const float* Wk    = (const float*)d_in[3];
    const float* bk    = (const float*)d_in[4];
    const float* Wv    = (const float*)d_in[5];
    const float* bv    = (const float*)d_in[6];
    const float* Wo    = (const float*)d_in[7];
    const float* bo    = (const float*)d_in[8];
    const float* ln1_g = (const float*)d_in[9];
    const float* ln1_b = (const float*)d_in[10];
    const float* W1    = (const float*)d_in[11];
    const float* b1    = (const float*)d_in[12];
    const float* W2    = (const float*)d_in[13];
    const float* b2    = (const float*)d_in[14];
    const float* ln2_g = (const float*)d_in[15];
    const float* ln2_b = (const float*)d_in[16];
    const float* Wc    = (const float*)d_in[17];
    const float* bc    = (const float*)d_in[18];
    float* out = (float*)d_out;

    float *tmp, *out1, *out2;
    cudaGetSymbolAddress((void**)&tmp,  g_tmp);
    cudaGetSymbolAddress((void**)&out1, g_out1);
    cudaGetSymbolAddress((void**)&out2, g_out2);

    __nv_bfloat16 *xh,*xl,*qbh,*qbl,*kbh,*kbl,*vbh,*vbl,*ah,*al,*o1h,*o1l,*fh,*fl,*o2h,*o2l;
    __nv_bfloat16 *wqh,*wql,*wkh,*wkl,*wvh,*wvl,*woh,*wol,*w1h,*w1l,*w2h,*w2l,*wch,*wcl;
    cudaGetSymbolAddress((void**)&xh,  g_xh);  cudaGetSymbolAddress((void**)&xl,  g_xl);
    cudaGetSymbolAddress((void**)&qbh, g_qbh); cudaGetSymbolAddress((void**)&qbl, g_qbl);
    cudaGetSymbolAddress((void**)&kbh, g_kbh); cudaGetSymbolAddress((void**)&kbl, g_kbl);
    cudaGetSymbolAddress((void**)&vbh, g_vbh); cudaGetSymbolAddress((void**)&vbl, g_vbl);
    cudaGetSymbolAddress((void**)&ah,  g_ah);  cudaGetSymbolAddress((void**)&al,  g_al);
    cudaGetSymbolAddress((void**)&o1h, g_o1h); cudaGetSymbolAddress((void**)&o1l, g_o1l);
    cudaGetSymbolAddress((void**)&fh,  g_fh);  cudaGetSymbolAddress((void**)&fl,  g_fl);
    cudaGetSymbolAddress((void**)&o2h, g_o2h); cudaGetSymbolAddress((void**)&o2l, g_o2l);
    cudaGetSymbolAddress((void**)&wqh, g_wqh); cudaGetSymbolAddress((void**)&wql, g_wql);
    cudaGetSymbolAddress((void**)&wkh, g_wkh); cudaGetSymbolAddress((void**)&wkl, g_wkl);
    cudaGetSymbolAddress((void**)&wvh, g_wvh); cudaGetSymbolAddress((void**)&wvl, g_wvl);
    cudaGetSymbolAddress((void**)&woh, g_woh); cudaGetSymbolAddress((void**)&wol, g_wol);
    cudaGetSymbolAddress((void**)&w1h, g_w1h); cudaGetSymbolAddress((void**)&w1l, g_w1l);
    cudaGetSymbolAddress((void**)&w2h, g_w2h); cudaGetSymbolAddress((void**)&w2l, g_w2l);
    cudaGetSymbolAddress((void**)&wch, g_wch); cudaGetSymbolAddress((void**)&wcl, g_wcl);

    cudaFuncSetAttribute(gemm_mma<0,1,0>,
                         cudaFuncAttributeMaxDynamicSharedMemorySize, GEMM_SMEM);
    cudaFuncSetAttribute(gemm_mma<0,0,1>,
                         cudaFuncAttributeMaxDynamicSharedMemorySize, GEMM_SMEM);
    cudaFuncSetAttribute(gemm_mma<1,0,1>,
                         cudaFuncAttributeMaxDynamicSharedMemorySize, GEMM_SMEM);
    cudaFuncSetAttribute(attn_mma,
                         cudaFuncAttributeMaxDynamicSharedMemorySize, ATTN_SMEM);

    const dim3 tb(32, 8);

    // --- weight prep (transpose + split) ---
    transpose_split<<<dim3(EE/32, CC/32), tb>>>(Wq, wqh, wql, CC, EE);
    transpose_split<<<dim3(EE/32, CC/32), tb>>>(Wk, wkh, wkl, CC, EE);
    transpose_split<<<dim3(EE/32, CC/32), tb>>>(Wv, wvh, wvl, CC, EE);
    transpose_split<<<dim3(CC/32, EE/32), tb>>>(Wo, woh, wol, EE, CC);
    transpose_split<<<dim3(FF/32, CC/32), tb>>>(W1, w1h, w1l, CC, FF);
    transpose_split<<<dim3(CC/32, FF/32), tb>>>(W2, w2h, w2l, FF, CC);
    convert_split<<<1024, 256>>>(Wc, wch, wcl, CC*CC);   // Wc already [N,K]

    // --- x split ---
    convert_split<<<2048, 256>>>(x, xh, xl, MM*CC);

    // --- QKV projections (bf16 hi/lo outputs) ---
    const dim3 gC(CC/128, MM/128);
    const dim3 gF(FF/128, MM/128);
    gemm_mma<0,0,1><<<gC, 256, GEMM_SMEM>>>(xh, xl, wqh, wql, bq, nullptr, qbh, qbl, MM, EE, CC);
    gemm_mma<0,0,1><<<gC, 256, GEMM_SMEM>>>(xh, xl, wkh, wkl, bk, nullptr, kbh, kbl, MM, EE, CC);
    gemm_mma<0,0,1><<<gC, 256, GEMM_SMEM>>>(xh, xl, wvh, wvl, bv, nullptr, vbh, vbl, MM, EE, CC);

    // --- tensor-core attention (hi/lo bf16 in & out) ---
    attn_mma<<<dim3(TT/128, BB*HH), 256, ATTN_SMEM>>>(
        qbh, qbl, kbh, kbl, vbh, vbl, ah, al);

    // --- output projection + residual + LN1 ---
    gemm_mma<0,1,0><<<gC, 256, GEMM_SMEM>>>(ah, al, woh, wol, bo, tmp, nullptr, nullptr, MM, CC, EE);
    add_ln<<<MM, 256>>>(x, tmp, ln1_g, ln1_b, out1, o1h, o1l);

    // --- FFN ---
    gemm_mma<1,0,1><<<gF, 256, GEMM_SMEM>>>(o1h, o1l, w1h, w1l, b1, nullptr, fh, fl, MM, FF, CC);
    gemm_mma<0,1,0><<<gC, 256, GEMM_SMEM>>>(fh, fl, w2h, w2l, b2, tmp, nullptr, nullptr, MM, CC, FF);
    add_ln<<<MM, 256>>>(out1, tmp, ln2_g, ln2_b, out2, o2h, o2l);

    // --- final pointwise conv: out = out2 @ Wc^T + bc ---
    gemm_mma<0,1,0><<<gC, 256, GEMM_SMEM>>>(o2h, o2l, wch, wcl, bc, out, nullptr, nullptr, MM, CC, CC);
}

// round 5
// speedup vs baseline: 3.6977x; 1.4656x over previous
#include <cuda_runtime.h>
#include <cuda_fp16.h>
#include <math.h>
#include <stdint.h>

// Problem dims (fixed)
#define BB   2
#define TT   2048
#define CC   1024
#define EE   1024
#define HH   16
#define HS   64
#define FF   4096
#define MM   (BB*TT)   // 4096 rows
#define QKV  (3*EE)    // 3072

// ======================= scratch (static device globals) ===================
__device__ float g_tmp [MM*CC];
__device__ float g_out1[MM*CC];
__device__ float g_out2[MM*CC];
__device__ float g_bqkv[QKV];

__device__ __half g_xh  [MM*CC],  g_xl  [MM*CC];
__device__ __half g_qkvh[MM*QKV], g_qkvl[MM*QKV];
__device__ __half g_ah  [MM*EE],  g_al  [MM*EE];
__device__ __half g_o1h [MM*CC],  g_o1l [MM*CC];
__device__ __half g_fh  [MM*FF],  g_fl  [MM*FF];
__device__ __half g_o2h [MM*CC],  g_o2l [MM*CC];
// transposed weights: [N, K] fp16 (single precision copy — rounding error 2^-12)
__device__ __half g_wqkv[QKV*CC];
__device__ __half g_wo  [CC*EE];
__device__ __half g_w1  [FF*CC];
__device__ __half g_w2  [CC*FF];
__device__ __half g_wc  [CC*CC];

// ======================= small PTX helpers =================================
__device__ __forceinline__ uint32_t smem_u32(const void* p) {
    uint32_t a;
    asm("{ .reg .u64 t; cvta.to.shared.u64 t, %1; cvt.u32.u64 %0, t; }"
        : "=r"(a) : "l"(p));
    return a;
}
__device__ __forceinline__ void cp16(uint32_t saddr, const void* gaddr) {
    asm volatile("cp.async.cg.shared.global [%0], [%1], 16;"
                 :: "r"(saddr), "l"(gaddr) : "memory");
}
#define CP_COMMIT() asm volatile("cp.async.commit_group;" ::: "memory")
#define CP_WAIT(n)  asm volatile("cp.async.wait_group %0;" :: "n"(n) : "memory")

__device__ __forceinline__ void ldsm_x4(uint32_t r[4], uint32_t addr) {
    asm volatile("ldmatrix.sync.aligned.m8n8.x4.shared.b16 {%0,%1,%2,%3}, [%4];"
                 : "=r"(r[0]), "=r"(r[1]), "=r"(r[2]), "=r"(r[3]) : "r"(addr));
}
__device__ __forceinline__ void mma16816(float c[4],
    uint32_t a0, uint32_t a1, uint32_t a2, uint32_t a3, uint32_t b0, uint32_t b1)
{
    asm volatile(
        "mma.sync.aligned.m16n8k16.row.col.f32.f16.f16.f32 "
        "{%0,%1,%2,%3}, {%4,%5,%6,%7}, {%8,%9}, {%0,%1,%2,%3};"
        : "+f"(c[0]), "+f"(c[1]), "+f"(c[2]), "+f"(c[3])
        : "r"(a0), "r"(a1), "r"(a2), "r"(a3), "r"(b0), "r"(b1));
}

__device__ __forceinline__ void split1h(float x, __half& h, __half& l) {
    h = __float2half_rn(x);
    l = __float2half_rn(x - __half2float(h));
}
__device__ __forceinline__ uint32_t packh(__half a, __half b) {
    __half2 t = __halves2half2(a, b);
    return *(uint32_t*)&t;
}

// ======================= conversion kernels ================================
__global__ __launch_bounds__(256) void convert_split_h(
    const float* __restrict__ in, __half* __restrict__ hi,
    __half* __restrict__ lo, int n)
{
    int idx = (blockIdx.x * blockDim.x + threadIdx.x) * 4;
    int stride = gridDim.x * blockDim.x * 4;
    for (; idx < n; idx += stride) {
        float4 v = *(const float4*)(in + idx);
        __half h0,h1,h2,h3,l0,l1,l2,l3;
        split1h(v.x,h0,l0); split1h(v.y,h1,l1); split1h(v.z,h2,l2); split1h(v.w,h3,l3);
        *(__half2*)(hi + idx)     = __halves2half2(h0,h1);
        *(__half2*)(hi + idx + 2) = __halves2half2(h2,h3);
        *(__half2*)(lo + idx)     = __halves2half2(l0,l1);
        *(__half2*)(lo + idx + 2) = __halves2half2(l2,l3);
    }
}

__global__ __launch_bounds__(256) void convert_half(
    const float* __restrict__ in, __half* __restrict__ o, int n)
{
    int idx = (blockIdx.x * blockDim.x + threadIdx.x) * 4;
    int stride = gridDim.x * blockDim.x * 4;
    for (; idx < n; idx += stride) {
        float4 v = *(const float4*)(in + idx);
        *(__half2*)(o + idx)     = __halves2half2(__float2half_rn(v.x), __float2half_rn(v.y));
        *(__half2*)(o + idx + 2) = __halves2half2(__float2half_rn(v.z), __float2half_rn(v.w));
    }
}

// W[K,N] fp32 -> Wt[N,K] fp16
__global__ __launch_bounds__(256) void transpose_half(
    const float* __restrict__ W, __half* __restrict__ T, int K, int N)
{
    __shared__ float t[32][33];
    int n0 = blockIdx.x * 32, k0 = blockIdx.y * 32;
    int tx = threadIdx.x, ty = threadIdx.y;
    #pragma unroll
    for (int s = 0; s < 32; s += 8)
        t[ty + s][tx] = W[(size_t)(k0 + ty + s) * N + n0 + tx];
    __syncthreads();
    #pragma unroll
    for (int s = 0; s < 32; s += 8) {
        float v = t[tx][ty + s];  // = W[k0+tx][n0+ty+s]
        T[(size_t)(n0 + ty + s) * K + k0 + tx] = __float2half_rn(v);
    }
}

// ======================= HMMA split-fp16 GEMM ==============================
// C[M,N] = (Ahi+Alo)[M,K] @ B[N,K]^T + bias; 2 MMA passes, fp32 accum.
// CTA tile 128x128, BK=32, 256 threads (8 warps, warp tile 64x32).
// Smem/stage: A_hi 8KB + A_lo 8KB + B 8KB = 24KB; double-buffered = 48KB.
#define STAGE_BYTES 24576
#define ARR_A_HI 0
#define ARR_A_LO 8192
#define ARR_B    16384
#define GEMM_SMEM (2*STAGE_BYTES)

__device__ __forceinline__ uint32_t sw_off(int row, int chunk) {
    return (uint32_t)(row * 64 + ((chunk ^ ((row >> 1) & 3)) << 4));
}

template<int GELU, int WF32, int WHILO>
__global__ __launch_bounds__(256) void gemm_mma(
    const __half* __restrict__ Ahi, const __half* __restrict__ Alo,
    const __half* __restrict__ Bw,
    const float* __restrict__ bias,
    float* __restrict__ Cf, __half* __restrict__ Chi, __half* __restrict__ Clo,
    int M, int N, int K)
{
    extern __shared__ char sm[];
    const uint32_t su = smem_u32(sm);

    const int tid  = threadIdx.x;
    const int wid  = tid >> 5;
    const int lane = tid & 31;
    const int m0 = blockIdx.y * 128;
    const int n0 = blockIdx.x * 128;
    const int wm0 = (wid & 1) * 64;
    const int wn0 = (wid >> 1) * 32;

    const int lr = tid >> 2;
    const int lq = tid & 3;

    float acc[4][4][4];
    #pragma unroll
    for (int mt = 0; mt < 4; mt++)
        #pragma unroll
        for (int nt = 0; nt < 4; nt++)
            #pragma unroll
            for (int i = 0; i < 4; i++) acc[mt][nt][i] = 0.f;

    const int nCh = K >> 5;

    auto issue = [&](int c, int stg) {
        const uint32_t sbase = su + stg * STAGE_BYTES;
        #pragma unroll
        for (int hh = 0; hh < 2; hh++) {
            const int r = lr + hh * 64;
            const size_t gA = ((size_t)(m0 + r) * K + c * 32 + lq * 8) * 2;
            const size_t gB = ((size_t)(n0 + r) * K + c * 32 + lq * 8) * 2;
            const uint32_t so = sw_off(r, lq);
            cp16(sbase + ARR_A_HI + so, (const char*)Ahi + gA);
            cp16(sbase + ARR_A_LO + so, (const char*)Alo + gA);
            cp16(sbase + ARR_B    + so, (const char*)Bw  + gB);
        }
    };

    issue(0, 0);
    CP_COMMIT();

    for (int c = 0; c < nCh; c++) {
        const int stg = c & 1;
        if (c + 1 < nCh) {
            issue(c + 1, stg ^ 1);
            CP_COMMIT();
            CP_WAIT(1);
        } else {
            CP_WAIT(0);
        }
        __syncthreads();

        const uint32_t sbase = su + stg * STAGE_BYTES;

        #pragma unroll
        for (int ks = 0; ks < 2; ks++) {
            // B fragments (single fp16), warp covers n = wn0..wn0+31
            uint32_t bfr[4][2];
            const int grp = lane >> 3, wi = lane & 7;
            const int brow_base = wn0 + wi + ((grp >> 1) << 3);
            const int bchunk = ks * 2 + (grp & 1);
            #pragma unroll
            for (int bt = 0; bt < 2; bt++) {
                uint32_t r4[4];
                const int br = brow_base + bt * 16;
                ldsm_x4(r4, sbase + ARR_B + sw_off(br, bchunk));
                bfr[bt*2][0]   = r4[0]; bfr[bt*2][1]   = r4[1];
                bfr[bt*2+1][0] = r4[2]; bfr[bt*2+1][1] = r4[3];
            }

            const int arow = wm0 + (lane & 15);
            const int achunk = ks * 2 + (lane >> 4);
            uint32_t a[4][4];
            #pragma unroll
            for (int mt = 0; mt < 4; mt++)
                ldsm_x4(a[mt], sbase + ARR_A_HI + sw_off(arow + mt * 16, achunk));
            #pragma unroll
            for (int mt = 0; mt < 4; mt++)
                #pragma unroll
                for (int nt = 0; nt < 4; nt++)
                    mma16816(acc[mt][nt], a[mt][0], a[mt][1], a[mt][2], a[mt][3],
                             bfr[nt][0], bfr[nt][1]);

            #pragma unroll
            for (int mt = 0; mt < 4; mt++)
                ldsm_x4(a[mt], sbase + ARR_A_LO + sw_off(arow + mt * 16, achunk));
            #pragma unroll
            for (int mt = 0; mt < 4; mt++)
                #pragma unroll
                for (int nt = 0; nt < 4; nt++)
                    mma16816(acc[mt][nt], a[mt][0], a[mt][1], a[mt][2], a[mt][3],
                             bfr[nt][0], bfr[nt][1]);
        }
        __syncthreads();
    }

    const int er = lane >> 2;
    const int ec = (lane & 3) * 2;
    #pragma unroll
    for (int mt = 0; mt < 4; mt++) {
        #pragma unroll
        for (int nt = 0; nt < 4; nt++) {
            const int col = n0 + wn0 + nt * 8 + ec;
            const float b0 = bias[col], b1 = bias[col + 1];
            const int rA = m0 + wm0 + mt * 16 + er;
            const int rB = rA + 8;
            float v00 = acc[mt][nt][0] + b0;
            float v01 = acc[mt][nt][1] + b1;
            float v10 = acc[mt][nt][2] + b0;
            float v11 = acc[mt][nt][3] + b1;
            if (GELU) {
                v00 = 0.5f * v00 * (1.0f + erff(v00 * 0.70710678118654752f));
                v01 = 0.5f * v01 * (1.0f + erff(v01 * 0.70710678118654752f));
                v10 = 0.5f * v10 * (1.0f + erff(v10 * 0.70710678118654752f));
                v11 = 0.5f * v11 * (1.0f + erff(v11 * 0.70710678118654752f));
            }
            if (WF32) {
                *(float2*)(Cf + (size_t)rA * N + col) = make_float2(v00, v01);
                *(float2*)(Cf + (size_t)rB * N + col) = make_float2(v10, v11);
            }
            if (WHILO) {
                __half h0,l0,h1,l1;
                split1h(v00,h0,l0); split1h(v01,h1,l1);
                *(__half2*)(Chi + (size_t)rA * N + col) = __halves2half2(h0,h1);
                *(__half2*)(Clo + (size_t)rA * N + col) = __halves2half2(l0,l1);
                split1h(v10,h0,l0); split1h(v11,h1,l1);
                *(__half2*)(Chi + (size_t)rB * N + col) = __halves2half2(h0,h1);
                *(__half2*)(Clo + (size_t)rB * N + col) = __halves2half2(l0,l1);
            }
        }
    }
}

// ======================= tensor-core flash attention =======================
// Reads Q/K/V from the fused QKV buffer (row stride 3072).
// S = (Qh+Ql)K^T (2 passes), online softmax, O += (Ph+Pl)V (2 passes).
// Smem: Qh/Ql [128][64] (16KB ea), K [64][64] (8KB), Vt [64][64] (8KB) = 48KB.
#define ASM_QH 0
#define ASM_QL 16384
#define ASM_K  32768
#define ASM_VT 40960
#define ATTN_SMEM 49152

__device__ __forceinline__ uint32_t sw8(int row, int ch) {
    return (uint32_t)(row * 128 + ((ch ^ (row & 7)) << 4));
}

__global__ void __launch_bounds__(256, 2) attn_mma(
    const __half* __restrict__ QKVh, const __half* __restrict__ QKVl,
    __half* __restrict__ Ohi, __half* __restrict__ Olo)
{
    extern __shared__ char sm[];
    const uint32_t su = smem_u32(sm);

    const int tid  = threadIdx.x;
    const int wid  = tid >> 5;
    const int lane = tid & 31;
    const int q0 = blockIdx.x * 128;
    const int bh = blockIdx.y;
    const int b  = bh >> 4;
    const int h  = bh & 15;
    const size_t mrow0 = (size_t)b * TT;            // batch's first global row
    const size_t qbase = (mrow0 + q0) * QKV + h * HS;

    const int wm  = wid * 16;
    const int grp = lane >> 3, wi = lane & 7;

    // ---- Q tile (hi+lo) load once: 128 rows x 8 chunks
    #pragma unroll
    for (int i = 0; i < 4; i++) {
        int vec = tid + i * 256;
        int row = vec >> 3, ch = vec & 7;
        const size_t g = (qbase + (size_t)row * QKV + ch * 8) * 2;
        cp16(su + ASM_QH + sw8(row, ch), (const char*)QKVh + g);
        cp16(su + ASM_QL + sw8(row, ch), (const char*)QKVl + g);
    }
    CP_COMMIT();

    float m0 = -1e30f, m1 = -1e30f, l0 = 0.f, l1 = 0.f;
    float oacc[8][4];
    #pragma unroll
    for (int nt = 0; nt < 8; nt++)
        #pragma unroll
        for (int i = 0; i < 4; i++) oacc[nt][i] = 0.f;

    for (int s0 = 0; s0 < TT; s0 += 64) {
        __syncthreads();   // all warps done reading K/V smem of prev chunk

        // K chunk (hi only): 64 rows x 8 chunks
        const size_t kbase = (mrow0 + s0) * QKV + EE + h * HS;
        #pragma unroll
        for (int i = 0; i < 2; i++) {
            int vec = tid + i * 256;
            int row = vec >> 3, ch = vec & 7;
            const size_t g = (kbase + (size_t)row * QKV + ch * 8) * 2;
            cp16(su + ASM_K + sw8(row, ch), (const char*)QKVh + g);
        }
        CP_COMMIT();

        // V chunk (hi only): load + transpose to Vt[dim][key]
        {
            const int key = tid >> 2, dg = tid & 3;
            const size_t gb = (mrow0 + s0 + key) * QKV + 2*EE + h * HS + dg * 16;
            uint4 v0 = *(const uint4*)(QKVh + gb);
            uint4 v1 = *(const uint4*)(QKVh + gb + 8);
            const int kc = key >> 3;
            const uint32_t kb = (key & 7) * 2;
            const __half* e0 = (const __half*)&v0;
            const __half* e1 = (const __half*)&v1;
            #pragma unroll
            for (int j = 0; j < 8; j++) {
                int d0 = dg * 16 + j;
                int d1 = dg * 16 + 8 + j;
                *(__half*)(sm + ASM_VT + sw8(d0, kc) + kb) = e0[j];
                *(__half*)(sm + ASM_VT + sw8(d1, kc) + kb) = e1[j];
            }
        }
        CP_WAIT(0);
        __syncthreads();

        // ---- S = (Qh+Ql) K^T, 2 passes ----
        float sacc[8][4];
        #pragma unroll
        for (int nt = 0; nt < 8; nt++)
            #pragma unroll
            for (int i = 0; i < 4; i++) sacc[nt][i] = 0.f;

        #pragma unroll
        for (int ks = 0; ks < 4; ks++) {
            const int arow = wm + (lane & 15);
            const int achunk = ks * 2 + (lane >> 4);
            uint32_t qa[4], qb[4];
            ldsm_x4(qa, su + ASM_QH + sw8(arow, achunk));
            ldsm_x4(qb, su + ASM_QL + sw8(arow, achunk));

            uint32_t kf[8][2];
            #pragma unroll
            for (int bt = 0; bt < 4; bt++) {
                const int br = wi + ((grp >> 1) << 3) + bt * 16;
                const int bch = ks * 2 + (grp & 1);
                uint32_t r4[4];
                ldsm_x4(r4, su + ASM_K + sw8(br, bch));
                kf[bt*2][0] = r4[0]; kf[bt*2][1] = r4[1];
                kf[bt*2+1][0] = r4[2]; kf[bt*2+1][1] = r4[3];
            }
            #pragma unroll
            for (int nt = 0; nt < 8; nt++) {
                mma16816(sacc[nt], qa[0], qa[1], qa[2], qa[3], kf[nt][0], kf[nt][1]);
                mma16816(sacc[nt], qb[0], qb[1], qb[2], qb[3], kf[nt][0], kf[nt][1]);
            }
        }

        // ---- online softmax ----
        float rmax0 = -1e30f, rmax1 = -1e30f;
        #pragma unroll
        for (int nt = 0; nt < 8; nt++) {
            #pragma unroll
            for (int i = 0; i < 4; i++) sacc[nt][i] *= 0.125f;
            rmax0 = fmaxf(rmax0, fmaxf(sacc[nt][0], sacc[nt][1]));
            rmax1 = fmaxf(rmax1, fmaxf(sacc[nt][2], sacc[nt][3]));
        }
        #pragma unroll
        for (int msk = 1; msk < 4; msk <<= 1) {
            rmax0 = fmaxf(rmax0, __shfl_xor_sync(0xffffffffu, rmax0, msk));
            rmax1 = fmaxf(rmax1, __shfl_xor_sync(0xffffffffu, rmax1, msk));
        }
        const float nm0 = fmaxf(m0, rmax0);
        const float nm1 = fmaxf(m1, rmax1);
        const float corr0 = __expf(m0 - nm0);
        const float corr1 = __expf(m1 - nm1);

        uint32_t pah[4][4], pal[4][4];
        float sum0 = 0.f, sum1 = 0.f;
        #pragma unroll
        for (int nt = 0; nt < 8; nt++) {
            float p0 = __expf(sacc[nt][0] - nm0);
            float p1 = __expf(sacc[nt][1] - nm0);
            float p2 = __expf(sacc[nt][2] - nm1);
            float p3 = __expf(sacc[nt][3] - nm1);
            sum0 += p0 + p1;
            sum1 += p2 + p3;
            __half h0,lo0,h1,lo1,h2,lo2,h3,lo3;
            split1h(p0,h0,lo0); split1h(p1,h1,lo1);
            split1h(p2,h2,lo2); split1h(p3,h3,lo3);
            const int kt = nt >> 1, hf = nt & 1;
            pah[kt][hf*2]   = packh(h0, h1);
            pah[kt][hf*2+1] = packh(h2, h3);
            pal[kt][hf*2]   = packh(lo0, lo1);
            pal[kt][hf*2+1] = packh(lo2, lo3);
        }
        #pragma unroll
        for (int msk = 1; msk < 4; msk <<= 1) {
            sum0 += __shfl_xor_sync(0xffffffffu, sum0, msk);
            sum1 += __shfl_xor_sync(0xffffffffu, sum1, msk);
        }
        l0 = l0 * corr0 + sum0;
        l1 = l1 * corr1 + sum1;
        m0 = nm0; m1 = nm1;
        #pragma unroll
        for (int nt = 0; nt < 8; nt++) {
            oacc[nt][0] *= corr0; oacc[nt][1] *= corr0;
            oacc[nt][2] *= corr1; oacc[nt][3] *= corr1;
        }

        // ---- O += (Ph+Pl) V, 2 passes ----
        #pragma unroll
        for (int ks = 0; ks < 4; ks++) {
            uint32_t vf[8][2];
            #pragma unroll
            for (int bt = 0; bt < 4; bt++) {
                const int br = wi + ((grp >> 1) << 3) + bt * 16;
                const int bch = ks * 2 + (grp & 1);
                uint32_t r4[4];
                ldsm_x4(r4, su + ASM_VT + sw8(br, bch));
                vf[bt*2][0] = r4[0]; vf[bt*2][1] = r4[1];
                vf[bt*2+1][0] = r4[2]; vf[bt*2+1][1] = r4[3];
            }
            #pragma unroll
            for (int nt = 0; nt < 8; nt++) {
                mma16816(oacc[nt], pah[ks][0], pah[ks][1], pah[ks][2], pah[ks][3],
                         vf[nt][0], vf[nt][1]);
                mma16816(oacc[nt], pal[ks][0], pal[ks][1], pal[ks][2], pal[ks][3],
                         vf[nt][0], vf[nt][1]);
            }
        }
    }

    // ---- epilogue (output stride EE, feeds Wo GEMM) ----
    const float inv0 = 1.0f / l0;
    const float inv1 = 1.0f / l1;
    const int r = lane >> 2;
    const int qcol = 2 * (lane & 3);
    const size_t row0 = (mrow0 + q0 + wm + r) * EE + h * HS;
    const size_t row1 = row0 + (size_t)8 * EE;
    #pragma unroll
    for (int nt = 0; nt < 8; nt++) {
        const int col = nt * 8 + qcol;
        float v0 = oacc[nt][0] * inv0, v1 = oacc[nt][1] * inv0;
        float v2 = oacc[nt][2] * inv1, v3 = oacc[nt][3] * inv1;
        __half h0,lo0,h1,lo1;
        split1h(v0,h0,lo0); split1h(v1,h1,lo1);
        *(__half2*)(Ohi + row0 + col) = __halves2half2(h0,h1);
        *(__half2*)(Olo + row0 + col) = __halves2half2(lo0,lo1);
        split1h(v2,h0,lo0); split1h(v3,h1,lo1);
        *(__half2*)(Ohi + row1 + col) = __halves2half2(h0,h1);
        *(__half2*)(Olo + row1 + col) = __halves2half2(lo0,lo1);
    }
}

// ======================= residual add + LayerNorm ==========================
__global__ __launch_bounds__(256) void add_ln(
    const float* __restrict__ a, const float* __restrict__ bsrc,
    const float* __restrict__ g, const float* __restrict__ beta,
    float* __restrict__ out,
    __half* __restrict__ hi, __half* __restrict__ lo)
{
    const int row = blockIdx.x;
    const int tid = threadIdx.x;
    const float4 av = ((const float4*)(a    + (size_t)row * CC))[tid];
    const float4 bv = ((const float4*)(bsrc + (size_t)row * CC))[tid];
    float4 v = make_float4(av.x + bv.x, av.y + bv.y, av.z + bv.z, av.w + bv.w);

    float s  = v.x + v.y + v.z + v.w;
    float ss = v.x*v.x + v.y*v.y + v.z*v.z + v.w*v.w;
    #pragma unroll
    for (int msk = 16; msk; msk >>= 1) {
        s  += __shfl_xor_sync(0xffffffffu, s,  msk);
        ss += __shfl_xor_sync(0xffffffffu, ss, msk);
    }
    __shared__ float ws[8], wss[8];
    __shared__ float mu_s, rstd_s;
    const int w = tid >> 5, lane = tid & 31;
    if (lane == 0) { ws[w] = s; wss[w] = ss; }
    __syncthreads();
    if (tid == 0) {
        float S = 0.f, SS = 0.f;
        #pragma unroll
        for (int i = 0; i < 8; i++) { S += ws[i]; SS += wss[i]; }
        float mu  = S * (1.0f / CC);
        float var = SS * (1.0f / CC) - mu * mu;
        mu_s   = mu;
        rstd_s = rsqrtf(var + 1e-5f);
    }
    __syncthreads();
    const float mu = mu_s, rstd = rstd_s;
    const float4 gv = ((const float4*)g)[tid];
    const float4 bv2 = ((const float4*)beta)[tid];
    float4 ov;
    ov.x = (v.x - mu) * rstd * gv.x + bv2.x;
    ov.y = (v.y - mu) * rstd * gv.y + bv2.y;
    ov.z = (v.z - mu) * rstd * gv.z + bv2.z;
    ov.w = (v.w - mu) * rstd * gv.w + bv2.w;
    ((float4*)(out + (size_t)row * CC))[tid] = ov;

    if (hi) {
        __half h0,h1,h2,h3,l0,l1,l2,l3;
        split1h(ov.x,h0,l0); split1h(ov.y,h1,l1); split1h(ov.z,h2,l2); split1h(ov.w,h3,l3);
        size_t o = (size_t)row * CC + tid * 4;
        *(__half2*)(hi + o)     = __halves2half2(h0,h1);
        *(__half2*)(hi + o + 2) = __halves2half2(h2,h3);
        *(__half2*)(lo + o)     = __halves2half2(l0,l1);
        *(__half2*)(lo + o + 2) = __halves2half2(l2,l3);
    }
}

// ======================= launch ============================================
extern "C" void kernel_launch(void* const* d_in, const int* in_sizes, int n_in,
                              void* d_out, int out_size)
{
    const float* x     = (const float*)d_in[0];
    const float* Wq    = (const float*)d_in[1];
    const float* bq    = (const float*)d_in[2];
    const float* Wk    = (const float*)d_in[3];
    const float* bk    = (const float*)d_in[4];
    const float* Wv    = (const float*)d_in[5];
    const float* bv    = (const float*)d_in[6];
    const float* Wo    = (const float*)d_in[7];
    const float* bo    = (const float*)d_in[8];
    const float* ln1_g = (const float*)d_in[9];
    const float* ln1_b = (const float*)d_in[10];
    const float* W1    = (const float*)d_in[11];
    const float* b1    = (const float*)d_in[12];
    const float* W2    = (const float*)d_in[13];
    const float* b2    = (const float*)d_in[14];
    const float* ln2_g = (const float*)d_in[15];
    const float* ln2_b = (const float*)d_in[16];
    const float* Wc    = (const float*)d_in[17];
    const float* bc    = (const float*)d_in[18];
    float* out = (float*)d_out;

    float *tmp, *out1, *out2, *bqkv;
    cudaGetSymbolAddress((void**)&tmp,  g_tmp);
    cudaGetSymbolAddress((void**)&out1, g_out1);
    cudaGetSymbolAddress((void**)&out2, g_out2);
    cudaGetSymbolAddress((void**)&bqkv, g_bqkv);

    __half *xh,*xl,*qkvh,*qkvl,*ah,*al,*o1h,*o1l,*fh,*fl,*o2h,*o2l;
    __half *wqkv,*wo,*w1,*w2,*wc;
    cudaGetSymbolAddress((void**)&xh,   g_xh);   cudaGetSymbolAddress((void**)&xl,   g_xl);
    cudaGetSymbolAddress((void**)&qkvh, g_qkvh); cudaGetSymbolAddress((void**)&qkvl, g_qkvl);
    cudaGetSymbolAddress((void**)&ah,   g_ah);   cudaGetSymbolAddress((void**)&al,   g_al);
    cudaGetSymbolAddress((void**)&o1h,  g_o1h);  cudaGetSymbolAddress((void**)&o1l,  g_o1l);
    cudaGetSymbolAddress((void**)&fh,   g_fh);   cudaGetSymbolAddress((void**)&fl,   g_fl);
    cudaGetSymbolAddress((void**)&o2h,  g_o2h);  cudaGetSymbolAddress((void**)&o2l,  g_o2l);
    cudaGetSymbolAddress((void**)&wqkv, g_wqkv);
    cudaGetSymbolAddress((void**)&wo,   g_wo);
    cudaGetSymbolAddress((void**)&w1,   g_w1);
    cudaGetSymbolAddress((void**)&w2,   g_w2);
    cudaGetSymbolAddress((void**)&wc,   g_wc);

    cudaFuncSetAttribute(gemm_mma<0,1,0>,
                         cudaFuncAttributeMaxDynamicSharedMemorySize, GEMM_SMEM);
    cudaFuncSetAttribute(gemm_mma<0,0,1>,
                         cudaFuncAttributeMaxDynamicSharedMemorySize, GEMM_SMEM);
    cudaFuncSetAttribute(gemm_mma<1,0,1>,
                         cudaFuncAttributeMaxDynamicSharedMemorySize, GEMM_SMEM);
    cudaFuncSetAttribute(attn_mma,
                         cudaFuncAttributeMaxDynamicSharedMemorySize, ATTN_SMEM);

    const dim3 tb(32, 8);

    // --- weight prep: transpose into fused [3E, C] + singles ---
    transpose_half<<<dim3(EE/32, CC/32), tb>>>(Wq, wqkv,           CC, EE);
    transpose_half<<<dim3(EE/32, CC/32), tb>>>(Wk, wqkv + EE*CC,   CC, EE);
    transpose_half<<<dim3(EE/32, CC/32), tb>>>(Wv, wqkv + 2*EE*CC, CC, EE);
    transpose_half<<<dim3(CC/32, EE/32), tb>>>(Wo, wo, EE, CC);
    transpose_half<<<dim3(FF/32, CC/32), tb>>>(W1, w1, CC, FF);
    transpose_half<<<dim3(CC/32, FF/32), tb>>>(W2, w2, FF, CC);
    convert_half<<<512, 256>>>(Wc, wc, CC*CC);   // Wc already [N,K]

    // --- fused qkv bias (D2D async copies are graph-capturable) ---
    cudaMemcpyAsync(bqkv,        bq, EE*sizeof(float), cudaMemcpyDeviceToDevice);
    cudaMemcpyAsync(bqkv + EE,   bk, EE*sizeof(float), cudaMemcpyDeviceToDevice);
    cudaMemcpyAsync(bqkv + 2*EE, bv, EE*sizeof(float), cudaMemcpyDeviceToDevice);

    // --- x split ---
    convert_split_h<<<2048, 256>>>(x, xh, xl, MM*CC);

    // --- fused QKV projection (N = 3072) ---
    const dim3 gQKV(QKV/128, MM/128);
    const dim3 gC(CC/128, MM/128);
    const dim3 gF(FF/128, MM/128);
    gemm_mma<0,0,1><<<gQKV, 256, GEMM_SMEM>>>(xh, xl, wqkv, bqkv,
                                              nullptr, qkvh, qkvl, MM, QKV, CC);

    // --- tensor-core attention ---
    attn_mma<<<dim3(TT/128, BB*HH), 256, ATTN_SMEM>>>(qkvh, qkvl, ah, al);

    // --- output projection + residual + LN1 ---
    gemm_mma<0,1,0><<<gC, 256, GEMM_SMEM>>>(ah, al, wo, bo, tmp, nullptr, nullptr, MM, CC, EE);
    add_ln<<<MM, 256>>>(x, tmp, ln1_g, ln1_b, out1, o1h, o1l);

    // --- FFN ---
    gemm_mma<1,0,1><<<gF, 256, GEMM_SMEM>>>(o1h, o1l, w1, b1, nullptr, fh, fl, MM, FF, CC);
    gemm_mma<0,1,0><<<gC, 256, GEMM_SMEM>>>(fh, fl, w2, b2, tmp, nullptr, nullptr, MM, CC, FF);
    add_ln<<<MM, 256>>>(out1, tmp, ln2_g, ln2_b, out2, o2h, o2l);

    // --- final pointwise conv: out = out2 @ Wc^T + bc ---
    gemm_mma<0,1,0><<<gC, 256, GEMM_SMEM>>>(o2h, o2l, wc, bc, out, nullptr, nullptr, MM, CC, CC);
}

// round 6
// speedup vs baseline: 5.8490x; 1.5818x over previous
#include <cuda_runtime.h>
#include <cuda_fp16.h>
#include <math.h>
#include <stdint.h>

// Problem dims (fixed)
#define BB   2
#define TT   2048
#define CC   1024
#define EE   1024
#define HH   16
#define HS   64
#define FF   4096
#define MM   (BB*TT)   // 4096 rows
#define QKV  (3*EE)    // 3072

// ======================= scratch (static device globals) ===================
__device__ float g_tmp [MM*CC];
__device__ float g_out1[MM*CC];
__device__ float g_out2[MM*CC];
__device__ float g_bqkv[QKV];

__device__ __half g_x16 [MM*CC];
__device__ __half g_qkv [MM*QKV];
__device__ __half g_a16 [MM*EE];
__device__ __half g_o116[MM*CC];
__device__ __half g_f16 [MM*FF];
__device__ __half g_o216[MM*CC];
// transposed weights: [N, K] fp16
__device__ __half g_wqkv[QKV*CC];
__device__ __half g_wo  [CC*EE];
__device__ __half g_w1  [FF*CC];
__device__ __half g_w2  [CC*FF];
__device__ __half g_wc  [CC*CC];

// ======================= small PTX helpers =================================
__device__ __forceinline__ uint32_t smem_u32(const void* p) {
    uint32_t a;
    asm("{ .reg .u64 t; cvta.to.shared.u64 t, %1; cvt.u32.u64 %0, t; }"
        : "=r"(a) : "l"(p));
    return a;
}
__device__ __forceinline__ void cp16(uint32_t saddr, const void* gaddr) {
    asm volatile("cp.async.cg.shared.global [%0], [%1], 16;"
                 :: "r"(saddr), "l"(gaddr) : "memory");
}
#define CP_COMMIT() asm volatile("cp.async.commit_group;" ::: "memory")
#define CP_WAIT(n)  asm volatile("cp.async.wait_group %0;" :: "n"(n) : "memory")

__device__ __forceinline__ void ldsm_x4(uint32_t r[4], uint32_t addr) {
    asm volatile("ldmatrix.sync.aligned.m8n8.x4.shared.b16 {%0,%1,%2,%3}, [%4];"
                 : "=r"(r[0]), "=r"(r[1]), "=r"(r[2]), "=r"(r[3]) : "r"(addr));
}
__device__ __forceinline__ void mma16816(float c[4],
    uint32_t a0, uint32_t a1, uint32_t a2, uint32_t a3, uint32_t b0, uint32_t b1)
{
    asm volatile(
        "mma.sync.aligned.m16n8k16.row.col.f32.f16.f16.f32 "
        "{%0,%1,%2,%3}, {%4,%5,%6,%7}, {%8,%9}, {%0,%1,%2,%3};"
        : "+f"(c[0]), "+f"(c[1]), "+f"(c[2]), "+f"(c[3])
        : "r"(a0), "r"(a1), "r"(a2), "r"(a3), "r"(b0), "r"(b1));
}
__device__ __forceinline__ uint32_t packh(__half a, __half b) {
    __half2 t = __halves2half2(a, b);
    return *(uint32_t*)&t;
}

// ======================= conversion kernels ================================
__global__ __launch_bounds__(256) void convert_half(
    const float* __restrict__ in, __half* __restrict__ o, int n)
{
    int idx = (blockIdx.x * blockDim.x + threadIdx.x) * 4;
    int stride = gridDim.x * blockDim.x * 4;
    for (; idx < n; idx += stride) {
        float4 v = *(const float4*)(in + idx);
        *(__half2*)(o + idx)     = __halves2half2(__float2half_rn(v.x), __float2half_rn(v.y));
        *(__half2*)(o + idx + 2) = __halves2half2(__float2half_rn(v.z), __float2half_rn(v.w));
    }
}

// W[K,N] fp32 -> Wt[N,K] fp16
__global__ __launch_bounds__(256) void transpose_half(
    const float* __restrict__ W, __half* __restrict__ T, int K, int N)
{
    __shared__ float t[32][33];
    int n0 = blockIdx.x * 32, k0 = blockIdx.y * 32;
    int tx = threadIdx.x, ty = threadIdx.y;
    #pragma unroll
    for (int s = 0; s < 32; s += 8)
        t[ty + s][tx] = W[(size_t)(k0 + ty + s) * N + n0 + tx];
    __syncthreads();
    #pragma unroll
    for (int s = 0; s < 32; s += 8) {
        float v = t[tx][ty + s];
        T[(size_t)(n0 + ty + s) * K + k0 + tx] = __float2half_rn(v);
    }
}

// ======================= HMMA fp16 GEMM ====================================
// C[M,N] = A[M,K] @ B[N,K]^T + bias; single pass, fp32 accum.
// CTA tile 128x128, BK=32, 256 threads (8 warps, warp tile 64x32).
// Smem/stage: A 8KB + B 8KB = 16KB; double-buffered = 32KB.
#define STAGE_BYTES 16384
#define ARR_A 0
#define ARR_B 8192
#define GEMM_SMEM (2*STAGE_BYTES)

__device__ __forceinline__ uint32_t sw_off(int row, int chunk) {
    return (uint32_t)(row * 64 + ((chunk ^ ((row >> 1) & 3)) << 4));
}

template<int GELU, int WF32, int WH>
__global__ __launch_bounds__(256) void gemm_mma(
    const __half* __restrict__ A, const __half* __restrict__ Bw,
    const float* __restrict__ bias,
    float* __restrict__ Cf, __half* __restrict__ Ch,
    int M, int N, int K)
{
    extern __shared__ char sm[];
    const uint32_t su = smem_u32(sm);

    const int tid  = threadIdx.x;
    const int wid  = tid >> 5;
    const int lane = tid & 31;
    const int m0 = blockIdx.y * 128;
    const int n0 = blockIdx.x * 128;
    const int wm0 = (wid & 1) * 64;
    const int wn0 = (wid >> 1) * 32;

    const int lr = tid >> 2;
    const int lq = tid & 3;

    float acc[4][4][4];
    #pragma unroll
    for (int mt = 0; mt < 4; mt++)
        #pragma unroll
        for (int nt = 0; nt < 4; nt++)
            #pragma unroll
            for (int i = 0; i < 4; i++) acc[mt][nt][i] = 0.f;

    const int nCh = K >> 5;

    auto issue = [&](int c, int stg) {
        const uint32_t sbase = su + stg * STAGE_BYTES;
        #pragma unroll
        for (int hh = 0; hh < 2; hh++) {
            const int r = lr + hh * 64;
            const size_t gA = ((size_t)(m0 + r) * K + c * 32 + lq * 8) * 2;
            const size_t gB = ((size_t)(n0 + r) * K + c * 32 + lq * 8) * 2;
            const uint32_t so = sw_off(r, lq);
            cp16(sbase + ARR_A + so, (const char*)A  + gA);
            cp16(sbase + ARR_B + so, (const char*)Bw + gB);
        }
    };

    issue(0, 0);
    CP_COMMIT();

    for (int c = 0; c < nCh; c++) {
        const int stg = c & 1;
        if (c + 1 < nCh) {
            issue(c + 1, stg ^ 1);
            CP_COMMIT();
            CP_WAIT(1);
        } else {
            CP_WAIT(0);
        }
        __syncthreads();

        const uint32_t sbase = su + stg * STAGE_BYTES;

        #pragma unroll
        for (int ks = 0; ks < 2; ks++) {
            uint32_t bfr[4][2];
            const int grp = lane >> 3, wi = lane & 7;
            const int brow_base = wn0 + wi + ((grp >> 1) << 3);
            const int bchunk = ks * 2 + (grp & 1);
            #pragma unroll
            for (int bt = 0; bt < 2; bt++) {
                uint32_t r4[4];
                const int br = brow_base + bt * 16;
                ldsm_x4(r4, sbase + ARR_B + sw_off(br, bchunk));
                bfr[bt*2][0]   = r4[0]; bfr[bt*2][1]   = r4[1];
                bfr[bt*2+1][0] = r4[2]; bfr[bt*2+1][1] = r4[3];
            }

            const int arow = wm0 + (lane & 15);
            const int achunk = ks * 2 + (lane >> 4);
            uint32_t a[4][4];
            #pragma unroll
            for (int mt = 0; mt < 4; mt++)
                ldsm_x4(a[mt], sbase + ARR_A + sw_off(arow + mt * 16, achunk));
            #pragma unroll
            for (int mt = 0; mt < 4; mt++)
                #pragma unroll
                for (int nt = 0; nt < 4; nt++)
                    mma16816(acc[mt][nt], a[mt][0], a[mt][1], a[mt][2], a[mt][3],
                             bfr[nt][0], bfr[nt][1]);
        }
        __syncthreads();
    }

    const int er = lane >> 2;
    const int ec = (lane & 3) * 2;
    #pragma unroll
    for (int mt = 0; mt < 4; mt++) {
        #pragma unroll
        for (int nt = 0; nt < 4; nt++) {
            const int col = n0 + wn0 + nt * 8 + ec;
            const float b0 = bias[col], b1 = bias[col + 1];
            const int rA = m0 + wm0 + mt * 16 + er;
            const int rB = rA + 8;
            float v00 = acc[mt][nt][0] + b0;
            float v01 = acc[mt][nt][1] + b1;
            float v10 = acc[mt][nt][2] + b0;
            float v11 = acc[mt][nt][3] + b1;
            if (GELU) {
                v00 = 0.5f * v00 * (1.0f + erff(v00 * 0.70710678118654752f));
                v01 = 0.5f * v01 * (1.0f + erff(v01 * 0.70710678118654752f));
                v10 = 0.5f * v10 * (1.0f + erff(v10 * 0.70710678118654752f));
                v11 = 0.5f * v11 * (1.0f + erff(v11 * 0.70710678118654752f));
            }
            if (WF32) {
                *(float2*)(Cf + (size_t)rA * N + col) = make_float2(v00, v01);
                *(float2*)(Cf + (size_t)rB * N + col) = make_float2(v10, v11);
            }
            if (WH) {
                *(__half2*)(Ch + (size_t)rA * N + col) =
                    __halves2half2(__float2half_rn(v00), __float2half_rn(v01));
                *(__half2*)(Ch + (size_t)rB * N + col) =
                    __halves2half2(__float2half_rn(v10), __float2half_rn(v11));
            }
        }
    }
}

// ======================= tensor-core flash attention =======================
// Reads Q/K/V from fused QKV buffer (row stride 3072). Single fp16 pass.
// Smem: Q [128][64] 16KB, K [64][64] 8KB, Vt [64][64] 8KB = 32KB.
#define ASM_Q  0
#define ASM_K  16384
#define ASM_VT 24576
#define ATTN_SMEM 32768

__device__ __forceinline__ uint32_t sw8(int row, int ch) {
    return (uint32_t)(row * 128 + ((ch ^ (row & 7)) << 4));
}

__global__ void __launch_bounds__(256, 2) attn_mma(
    const __half* __restrict__ QKVp, __half* __restrict__ O)
{
    extern __shared__ char sm[];
    const uint32_t su = smem_u32(sm);

    const int tid  = threadIdx.x;
    const int wid  = tid >> 5;
    const int lane = tid & 31;
    const int q0 = blockIdx.x * 128;
    const int bh = blockIdx.y;
    const int b  = bh >> 4;
    const int h  = bh & 15;
    const size_t mrow0 = (size_t)b * TT;
    const size_t qbase = (mrow0 + q0) * QKV + h * HS;

    const int wm  = wid * 16;
    const int grp = lane >> 3, wi = lane & 7;

    // Q tile load once: 128 rows x 8 chunks
    #pragma unroll
    for (int i = 0; i < 4; i++) {
        int vec = tid + i * 256;
        int row = vec >> 3, ch = vec & 7;
        const size_t g = (qbase + (size_t)row * QKV + ch * 8) * 2;
        cp16(su + ASM_Q + sw8(row, ch), (const char*)QKVp + g);
    }
    CP_COMMIT();

    float m0 = -1e30f, m1 = -1e30f, l0 = 0.f, l1 = 0.f;
    float oacc[8][4];
    #pragma unroll
    for (int nt = 0; nt < 8; nt++)
        #pragma unroll
        for (int i = 0; i < 4; i++) oacc[nt][i] = 0.f;

    for (int s0 = 0; s0 < TT; s0 += 64) {
        __syncthreads();

        // K chunk
        const size_t kbase = (mrow0 + s0) * QKV + EE + h * HS;
        #pragma unroll
        for (int i = 0; i < 2; i++) {
            int vec = tid + i * 256;
            int row = vec >> 3, ch = vec & 7;
            const size_t g = (kbase + (size_t)row * QKV + ch * 8) * 2;
            cp16(su + ASM_K + sw8(row, ch), (const char*)QKVp + g);
        }
        CP_COMMIT();

        // V chunk: load + transpose to Vt[dim][key]
        {
            const int key = tid >> 2, dg = tid & 3;
            const size_t gb = (mrow0 + s0 + key) * QKV + 2*EE + h * HS + dg * 16;
            uint4 v0 = *(const uint4*)(QKVp + gb);
            uint4 v1 = *(const uint4*)(QKVp + gb + 8);
            const int kc = key >> 3;
            const uint32_t kb = (key & 7) * 2;
            const __half* e0 = (const __half*)&v0;
            const __half* e1 = (const __half*)&v1;
            #pragma unroll
            for (int j = 0; j < 8; j++) {
                int d0 = dg * 16 + j;
                int d1 = dg * 16 + 8 + j;
                *(__half*)(sm + ASM_VT + sw8(d0, kc) + kb) = e0[j];
                *(__half*)(sm + ASM_VT + sw8(d1, kc) + kb) = e1[j];
            }
        }
        CP_WAIT(0);
        __syncthreads();

        // ---- S = Q K^T ----
        float sacc[8][4];
        #pragma unroll
        for (int nt = 0; nt < 8; nt++)
            #pragma unroll
            for (int i = 0; i < 4; i++) sacc[nt][i] = 0.f;

        #pragma unroll
        for (int ks = 0; ks < 4; ks++) {
            const int arow = wm + (lane & 15);
            const int achunk = ks * 2 + (lane >> 4);
            uint32_t qa[4];
            ldsm_x4(qa, su + ASM_Q + sw8(arow, achunk));

            uint32_t kf[8][2];
            #pragma unroll
            for (int bt = 0; bt < 4; bt++) {
                const int br = wi + ((grp >> 1) << 3) + bt * 16;
                const int bch = ks * 2 + (grp & 1);
                uint32_t r4[4];
                ldsm_x4(r4, su + ASM_K + sw8(br, bch));
                kf[bt*2][0] = r4[0]; kf[bt*2][1] = r4[1];
                kf[bt*2+1][0] = r4[2]; kf[bt*2+1][1] = r4[3];
            }
            #pragma unroll
            for (int nt = 0; nt < 8; nt++)
                mma16816(sacc[nt], qa[0], qa[1], qa[2], qa[3], kf[nt][0], kf[nt][1]);
        }

        // ---- online softmax ----
        float rmax0 = -1e30f, rmax1 = -1e30f;
        #pragma unroll
        for (int nt = 0; nt < 8; nt++) {
            #pragma unroll
            for (int i = 0; i < 4; i++) sacc[nt][i] *= 0.125f;
            rmax0 = fmaxf(rmax0, fmaxf(sacc[nt][0], sacc[nt][1]));
            rmax1 = fmaxf(rmax1, fmaxf(sacc[nt][2], sacc[nt][3]));
        }
        #pragma unroll
        for (int msk = 1; msk < 4; msk <<= 1) {
            rmax0 = fmaxf(rmax0, __shfl_xor_sync(0xffffffffu, rmax0, msk));
            rmax1 = fmaxf(rmax1, __shfl_xor_sync(0xffffffffu, rmax1, msk));
        }
        const float nm0 = fmaxf(m0, rmax0);
        const float nm1 = fmaxf(m1, rmax1);
        const float corr0 = __expf(m0 - nm0);
        const float corr1 = __expf(m1 - nm1);

        uint32_t pa[4][4];
        float sum0 = 0.f, sum1 = 0.f;
        #pragma unroll
        for (int nt = 0; nt < 8; nt++) {
            float p0 = __expf(sacc[nt][0] - nm0);
            float p1 = __expf(sacc[nt][1] - nm0);
            float p2 = __expf(sacc[nt][2] - nm1);
            float p3 = __expf(sacc[nt][3] - nm1);
            sum0 += p0 + p1;
            sum1 += p2 + p3;
            const int kt = nt >> 1, hf = nt & 1;
            pa[kt][hf*2]   = packh(__float2half_rn(p0), __float2half_rn(p1));
            pa[kt][hf*2+1] = packh(__float2half_rn(p2), __float2half_rn(p3));
        }
        #pragma unroll
        for (int msk = 1; msk < 4; msk <<= 1) {
            sum0 += __shfl_xor_sync(0xffffffffu, sum0, msk);
            sum1 += __shfl_xor_sync(0xffffffffu, sum1, msk);
        }
        l0 = l0 * corr0 + sum0;
        l1 = l1 * corr1 + sum1;
        m0 = nm0; m1 = nm1;
        #pragma unroll
        for (int nt = 0; nt < 8; nt++) {
            oacc[nt][0] *= corr0; oacc[nt][1] *= corr0;
            oacc[nt][2] *= corr1; oacc[nt][3] *= corr1;
        }

        // ---- O += P V ----
        #pragma unroll
        for (int ks = 0; ks < 4; ks++) {
            uint32_t vf[8][2];
            #pragma unroll
            for (int bt = 0; bt < 4; bt++) {
                const int br = wi + ((grp >> 1) << 3) + bt * 16;
                const int bch = ks * 2 + (grp & 1);
                uint32_t r4[4];
                ldsm_x4(r4, su + ASM_VT + sw8(br, bch));
                vf[bt*2][0] = r4[0]; vf[bt*2][1] = r4[1];
                vf[bt*2+1][0] = r4[2]; vf[bt*2+1][1] = r4[3];
            }
            #pragma unroll
            for (int nt = 0; nt < 8; nt++)
                mma16816(oacc[nt], pa[ks][0], pa[ks][1], pa[ks][2], pa[ks][3],
                         vf[nt][0], vf[nt][1]);
        }
    }

    // ---- epilogue (output stride EE, feeds Wo GEMM) ----
    const float inv0 = 1.0f / l0;
    const float inv1 = 1.0f / l1;
    const int r = lane >> 2;
    const int qcol = 2 * (lane & 3);
    const size_t row0 = (mrow0 + q0 + wm + r) * EE + h * HS;
    const size_t row1 = row0 + (size_t)8 * EE;
    #pragma unroll
    for (int nt = 0; nt < 8; nt++) {
        const int col = nt * 8 + qcol;
        *(__half2*)(O + row0 + col) = __halves2half2(
            __float2half_rn(oacc[nt][0] * inv0), __float2half_rn(oacc[nt][1] * inv0));
        *(__half2*)(O + row1 + col) = __halves2half2(
            __float2half_rn(oacc[nt][2] * inv1), __float2half_rn(oacc[nt][3] * inv1));
    }
}

// ======================= residual add + LayerNorm ==========================
__global__ __launch_bounds__(256) void add_ln(
    const float* __restrict__ a, const float* __restrict__ bsrc,
    const float* __restrict__ g, const float* __restrict__ beta,
    float* __restrict__ out, __half* __restrict__ oh)
{
    const int row = blockIdx.x;
    const int tid = threadIdx.x;
    const float4 av = ((const float4*)(a    + (size_t)row * CC))[tid];
    const float4 bv = ((const float4*)(bsrc + (size_t)row * CC))[tid];
    float4 v = make_float4(av.x + bv.x, av.y + bv.y, av.z + bv.z, av.w + bv.w);

    float s  = v.x + v.y + v.z + v.w;
    float ss = v.x*v.x + v.y*v.y + v.z*v.z + v.w*v.w;
    #pragma unroll
    for (int msk = 16; msk; msk >>= 1) {
        s  += __shfl_xor_sync(0xffffffffu, s,  msk);
        ss += __shfl_xor_sync(0xffffffffu, ss, msk);
    }
    __shared__ float ws[8], wss[8];
    __shared__ float mu_s, rstd_s;
    const int w = tid >> 5, lane = tid & 31;
    if (lane == 0) { ws[w] = s; wss[w] = ss; }
    __syncthreads();
    if (tid == 0) {
        float S = 0.f, SS = 0.f;
        #pragma unroll
        for (int i = 0; i < 8; i++) { S += ws[i]; SS += wss[i]; }
        float mu  = S * (1.0f / CC);
        float var = SS * (1.0f / CC) - mu * mu;
        mu_s   = mu;
        rstd_s = rsqrtf(var + 1e-5f);
    }
    __syncthreads();
    const float mu = mu_s, rstd = rstd_s;
    const float4 gv = ((const float4*)g)[tid];
    const float4 bv2 = ((const float4*)beta)[tid];
    float4 ov;
    ov.x = (v.x - mu) * rstd * gv.x + bv2.x;
    ov.y = (v.y - mu) * rstd * gv.y + bv2.y;
    ov.z = (v.z - mu) * rstd * gv.z + bv2.z;
    ov.w = (v.w - mu) * rstd * gv.w + bv2.w;
    ((float4*)(out + (size_t)row * CC))[tid] = ov;

    if (oh) {
        size_t o = (size_t)row * CC + tid * 4;
        *(__half2*)(oh + o)     = __halves2half2(__float2half_rn(ov.x), __float2half_rn(ov.y));
        *(__half2*)(oh + o + 2) = __halves2half2(__float2half_rn(ov.z), __float2half_rn(ov.w));
    }
}

// ======================= launch ============================================
extern "C" void kernel_launch(void* const* d_in, const int* in_sizes, int n_in,
                              void* d_out, int out_size)
{
    const float* x     = (const float*)d_in[0];
    const float* Wq    = (const float*)d_in[1];
    const float* bq    = (const float*)d_in[2];
    const float* Wk    = (const float*)d_in[3];
    const float* bk    = (const float*)d_in[4];
    const float* Wv    = (const float*)d_in[5];
    const float* bv    = (const float*)d_in[6];
    const float* Wo    = (const float*)d_in[7];
    const float* bo    = (const float*)d_in[8];
    const float* ln1_g = (const float*)d_in[9];
    const float* ln1_b = (const float*)d_in[10];
    const float* W1    = (const float*)d_in[11];
    const float* b1    = (const float*)d_in[12];
    const float* W2    = (const float*)d_in[13];
    const float* b2    = (const float*)d_in[14];
    const float* ln2_g = (const float*)d_in[15];
    const float* ln2_b = (const float*)d_in[16];
    const float* Wc    = (const float*)d_in[17];
    const float* bc    = (const float*)d_in[18];
    float* out = (float*)d_out;

    float *tmp, *out1, *out2, *bqkv;
    cudaGetSymbolAddress((void**)&tmp,  g_tmp);
    cudaGetSymbolAddress((void**)&out1, g_out1);
    cudaGetSymbolAddress((void**)&out2, g_out2);
    cudaGetSymbolAddress((void**)&bqkv, g_bqkv);

    __half *x16,*qkv,*a16,*o116,*f16,*o216,*wqkv,*wo,*w1,*w2,*wc;
    cudaGetSymbolAddress((void**)&x16,  g_x16);
    cudaGetSymbolAddress((void**)&qkv,  g_qkv);
    cudaGetSymbolAddress((void**)&a16,  g_a16);
    cudaGetSymbolAddress((void**)&o116, g_o116);
    cudaGetSymbolAddress((void**)&f16,  g_f16);
    cudaGetSymbolAddress((void**)&o216, g_o216);
    cudaGetSymbolAddress((void**)&wqkv, g_wqkv);
    cudaGetSymbolAddress((void**)&wo,   g_wo);
    cudaGetSymbolAddress((void**)&w1,   g_w1);
    cudaGetSymbolAddress((void**)&w2,   g_w2);
    cudaGetSymbolAddress((void**)&wc,   g_wc);

    cudaFuncSetAttribute(gemm_mma<0,1,0>,
                         cudaFuncAttributeMaxDynamicSharedMemorySize, GEMM_SMEM);
    cudaFuncSetAttribute(gemm_mma<0,0,1>,
                         cudaFuncAttributeMaxDynamicSharedMemorySize, GEMM_SMEM);
    cudaFuncSetAttribute(gemm_mma<1,0,1>,
                         cudaFuncAttributeMaxDynamicSharedMemorySize, GEMM_SMEM);
    cudaFuncSetAttribute(attn_mma,
                         cudaFuncAttributeMaxDynamicSharedMemorySize, ATTN_SMEM);

    const dim3 tb(32, 8);

    // --- weight prep ---
    transpose_half<<<dim3(EE/32, CC/32), tb>>>(Wq, wqkv,           CC, EE);
    transpose_half<<<dim3(EE/32, CC/32), tb>>>(Wk, wqkv + EE*CC,   CC, EE);
    transpose_half<<<dim3(EE/32, CC/32), tb>>>(Wv, wqkv + 2*EE*CC, CC, EE);
    transpose_half<<<dim3(CC/32, EE/32), tb>>>(Wo, wo, EE, CC);
    transpose_half<<<dim3(FF/32, CC/32), tb>>>(W1, w1, CC, FF);
    transpose_half<<<dim3(CC/32, FF/32), tb>>>(W2, w2, FF, CC);
    convert_half<<<512, 256>>>(Wc, wc, CC*CC);

    // --- fused qkv bias ---
    cudaMemcpyAsync(bqkv,        bq, EE*sizeof(float), cudaMemcpyDeviceToDevice);
    cudaMemcpyAsync(bqkv + EE,   bk, EE*sizeof(float), cudaMemcpyDeviceToDevice);
    cudaMemcpyAsync(bqkv + 2*EE, bv, EE*sizeof(float), cudaMemcpyDeviceToDevice);

    // --- x -> fp16 ---
    convert_half<<<2048, 256>>>(x, x16, MM*CC);

    // --- fused QKV projection (N = 3072) ---
    const dim3 gQKV(QKV/128, MM/128);
    const dim3 gC(CC/128, MM/128);
    const dim3 gF(FF/128, MM/128);
    gemm_mma<0,0,1><<<gQKV, 256, GEMM_SMEM>>>(x16, wqkv, bqkv, nullptr, qkv, MM, QKV, CC);

    // --- attention ---
    attn_mma<<<dim3(TT/128, BB*HH), 256, ATTN_SMEM>>>(qkv, a16);

    // --- output projection + residual + LN1 ---
    gemm_mma<0,1,0><<<gC, 256, GEMM_SMEM>>>(a16, wo, bo, tmp, nullptr, MM, CC, EE);
    add_ln<<<MM, 256>>>(x, tmp, ln1_g, ln1_b, out1, o116);

    // --- FFN ---
    gemm_mma<1,0,1><<<gF, 256, GEMM_SMEM>>>(o116, w1, b1, nullptr, f16, MM, FF, CC);
    gemm_mma<0,1,0><<<gC, 256, GEMM_SMEM>>>(f16, w2, b2, tmp, nullptr, MM, CC, FF);
    add_ln<<<MM, 256>>>(out1, tmp, ln2_g, ln2_b, out2, o216);

    // --- final pointwise conv: out = out2 @ Wc^T + bc ---
    gemm_mma<0,1,0><<<gC, 256, GEMM_SMEM>>>(o216, wc, bc, out, nullptr, MM, CC, CC);
}